// round 14
// baseline (speedup 1.0000x reference)
#include <cuda_runtime.h>
#include <math.h>
#include <stdint.h>

// Problem constants
#define BB   2
#define SEQ  2048
#define DM   1024
#define NH   16
#define DH   64
#define DFF  4096
#define MR   (BB * SEQ)   // 4096 rows

// k-permutation within 8-groups: storage order [0,4,1,5,2,6,3,7]

// ---------------------------------------------------------------------------
// Scratch
// ---------------------------------------------------------------------------
__device__ float g_h   [(size_t)MR * DM];      // LN1 out (perm)
__device__ float g_qkv [(size_t)MR * 3 * DM];  // QKV (features perm)
__device__ float g_o   [(size_t)MR * DM];      // attn out (features perm)
__device__ float g_src2[(size_t)MR * DM];      // residual (plain)
__device__ float g_f   [(size_t)MR * DM];      // LN2 out (perm)
__device__ float g_ffn [(size_t)MR * DFF];     // FFN hidden (perm)
__device__ float g_wq  [(size_t)3 * DM * DM];  // weights: k-perm
__device__ float g_wo  [(size_t)DM * DM];
__device__ float g_w1  [(size_t)DFF * DM];
__device__ float g_w2  [(size_t)DM * DFF];

// ---------------------------------------------------------------------------
// Helpers
// ---------------------------------------------------------------------------
__device__ __forceinline__ uint32_t smem_u32(const void* p) {
    uint32_t a;
    asm("{ .reg .u64 t; cvta.to.shared.u64 t, %1; cvt.u32.u64 %0, t; }" : "=r"(a) : "l"(p));
    return a;
}
__device__ __forceinline__ float rtf32(float x) {
    uint32_t r;
    asm("cvt.rna.tf32.f32 %0, %1;" : "=r"(r) : "f"(x));
    return __uint_as_float(r);
}

#define CP16(dst, src) \
    asm volatile("cp.async.cg.shared.global [%0], [%1], 16;" :: "r"(dst), "l"(src) : "memory")
#define CP_COMMIT()  asm volatile("cp.async.commit_group;" ::: "memory")
#define CP_WAIT(n)   asm volatile("cp.async.wait_group %0;" :: "n"(n) : "memory")

__device__ __forceinline__ void mma_tf32(float* d, const uint32_t* a, const uint32_t* b) {
    asm volatile(
        "mma.sync.aligned.m16n8k8.row.col.f32.tf32.tf32.f32 "
        "{%0,%1,%2,%3}, {%4,%5,%6,%7}, {%8,%9}, {%0,%1,%2,%3};"
        : "+f"(d[0]), "+f"(d[1]), "+f"(d[2]), "+f"(d[3])
        : "r"(a[0]), "r"(a[1]), "r"(a[2]), "r"(a[3]), "r"(b[0]), "r"(b[1]));
}

// ---------------------------------------------------------------------------
// Tensor-core GEMM (R11 frozen): k-permuted operands + XOR swizzle
// (group' = group ^ (row & 3)) -> conflict-free LDS.64 at SMS=32.
// 3 stages, 2 CTAs/SM. CTA 128x128; 8 warps 64x32; BK=32.
// flags: 1 = relu, 2 = tf32-round, 4 = permute output features
// ---------------------------------------------------------------------------
#define ATILE  (128 * 32)
#define STF    (2 * ATILE)
#define STAGES 3
#define GEMM_SMEM (STAGES * STF * 4)   // 98304 bytes

__global__ __launch_bounds__(256, 2) void mma_gemm(
    const float* __restrict__ A, const float* __restrict__ W,
    const float* __restrict__ bias, const float* __restrict__ res,
    float* __restrict__ C, int N, int K, int flags)
{
    extern __shared__ float sm[];

    int t    = threadIdx.x;
    int wid  = t >> 5, lane = t & 31;
    int m0   = blockIdx.y * 128, n0 = blockIdx.x * 128;
    int wm   = (wid >> 2) * 64;
    int wn   = (wid & 3) * 32;
    int lr   = lane >> 2;
    int lc   = lane & 3;
    int jx   = lr & 3;

    int tr  = t >> 3;
    int lg  = (t & 7) >> 1;
    int lw  = (t & 1) * 4;
    const float* Ag = A + (size_t)(m0 + tr) * K + (t & 7) * 4;
    const float* Wg = W + (size_t)(n0 + tr) * K + (t & 7) * 4;
    uint32_t sbase = smem_u32(sm);
    uint32_t sAoff = (uint32_t)((tr * 32 + ((lg ^ (tr & 3)) << 3) + lw) * 4);
    const uint32_t rowStep = 32 * 32 * 4;

    float acc[4][4][4];
    #pragma unroll
    for (int i = 0; i < 4; i++)
        #pragma unroll
        for (int j = 0; j < 4; j++)
            #pragma unroll
            for (int k = 0; k < 4; k++) acc[i][j][k] = 0.f;

    int NK = K >> 5;

    #pragma unroll
    for (int s = 0; s < STAGES - 1; s++) {
        uint32_t sA = sbase + (uint32_t)(s * STF * 4) + sAoff;
        uint32_t sB = sA + (uint32_t)(ATILE * 4);
        const float* Ap = Ag + (size_t)s * 32;
        const float* Wp = Wg + (size_t)s * 32;
        #pragma unroll
        for (int i = 0; i < 4; i++) {
            CP16(sA + i * rowStep, Ap + (size_t)(32 * i) * K);
            CP16(sB + i * rowStep, Wp + (size_t)(32 * i) * K);
        }
        CP_COMMIT();
    }

    for (int kt = 0; kt < NK; kt++) {
        int s = kt % STAGES;
        if (kt + 1 < NK) { CP_WAIT(1); } else { CP_WAIT(0); }
        __syncthreads();

        if (kt + STAGES - 1 < NK) {
            int ls = (kt + STAGES - 1) % STAGES;
            uint32_t sA = sbase + (uint32_t)(ls * STF * 4) + sAoff;
            uint32_t sB = sA + (uint32_t)(ATILE * 4);
            const float* Ap = Ag + (size_t)(kt + STAGES - 1) * 32;
            const float* Wp = Wg + (size_t)(kt + STAGES - 1) * 32;
            #pragma unroll
            for (int i = 0; i < 4; i++) {
                CP16(sA + i * rowStep, Ap + (size_t)(32 * i) * K);
                CP16(sB + i * rowStep, Wp + (size_t)(32 * i) * K);
            }
            CP_COMMIT();
        }

        const float* Ab = sm + s * STF;
        const float* Bb = Ab + ATILE;
        #pragma unroll
        for (int ks = 0; ks < 4; ks++) {
            int kcol = ((ks ^ jx) << 3) + 2 * lc;
            uint32_t a[4][4], b[4][2];
            #pragma unroll
            for (int mt = 0; mt < 4; mt++) {
                const float2* p0 = (const float2*)(Ab + (wm + mt * 16 + lr) * 32 + kcol);
                const float2* p1 = (const float2*)(Ab + (wm + mt * 16 + lr + 8) * 32 + kcol);
                float2 v0 = *p0, v1 = *p1;
                a[mt][0] = __float_as_uint(v0.x);
                a[mt][2] = __float_as_uint(v0.y);
                a[mt][1] = __float_as_uint(v1.x);
                a[mt][3] = __float_as_uint(v1.y);
            }
            #pragma unroll
            for (int nt = 0; nt < 4; nt++) {
                const float2* p = (const float2*)(Bb + (wn + nt * 8 + lr) * 32 + kcol);
                float2 v = *p;
                b[nt][0] = __float_as_uint(v.x);
                b[nt][1] = __float_as_uint(v.y);
            }
            #pragma unroll
            for (int mt = 0; mt < 4; mt++)
                #pragma unroll
                for (int nt = 0; nt < 4; nt++)
                    mma_tf32(acc[mt][nt], a[mt], b[nt]);
        }
    }

    bool do_relu  = (flags & 1) != 0;
    bool do_round = (flags & 2) != 0;
    bool do_perm  = (flags & 4) != 0;
    int f0 = 2 * lc;
    int pos0 = (f0 < 4) ? 2 * f0 : 2 * f0 - 7;
    #pragma unroll
    for (int mt = 0; mt < 4; mt++) {
        int row = m0 + wm + mt * 16 + lr;
        #pragma unroll
        for (int nt = 0; nt < 4; nt++) {
            int colt = n0 + wn + nt * 8 + f0;
            float b0 = __ldg(&bias[colt]), b1 = __ldg(&bias[colt + 1]);
            #pragma unroll
            for (int half = 0; half < 2; half++) {
                int r = row + half * 8;
                float v0 = acc[mt][nt][half * 2 + 0] + b0;
                float v1 = acc[mt][nt][half * 2 + 1] + b1;
                if (res) {
                    const float* rp = res + (size_t)r * N + colt;
                    v0 += rp[0]; v1 += rp[1];
                }
                if (do_relu)  { v0 = fmaxf(v0, 0.f); v1 = fmaxf(v1, 0.f); }
                if (do_round) { v0 = rtf32(v0); v1 = rtf32(v1); }
                if (do_perm) {
                    float* cp = C + (size_t)r * N + n0 + wn + nt * 8;
                    cp[pos0]     = v0;
                    cp[pos0 + 2] = v1;
                } else {
                    *(float2*)(C + (size_t)r * N + colt) = make_float2(v0, v1);
                }
            }
        }
    }
}

// ---------------------------------------------------------------------------
// Round weights to tf32 AND k-permute within 8-groups
// ---------------------------------------------------------------------------
__global__ __launch_bounds__(256) void round_w_kernel(
    const float4* __restrict__ in, float* __restrict__ out, int n4)
{
    int i = blockIdx.x * blockDim.x + threadIdx.x;
    if (i < n4) {
        float4 v = in[i];
        size_t f0 = (size_t)i * 4;
        size_t ob = (f0 & ~(size_t)7) + ((f0 >> 2) & 1);
        out[ob + 0] = rtf32(v.x);
        out[ob + 2] = rtf32(v.y);
        out[ob + 4] = rtf32(v.z);
        out[ob + 6] = rtf32(v.w);
    }
}

// ---------------------------------------------------------------------------
// LayerNorm: tf32-rounded, k-permuted output
// ---------------------------------------------------------------------------
__global__ __launch_bounds__(256) void ln_kernel(
    const float* __restrict__ x, const float* __restrict__ g,
    const float* __restrict__ bt, float* __restrict__ y)
{
    int row = blockIdx.x;
    int t = threadIdx.x;
    const float* xr = x + (size_t)row * DM;

    float4 v = *(const float4*)(xr + t * 4);
    float s  = v.x + v.y + v.z + v.w;
    float ss = v.x * v.x + v.y * v.y + v.z * v.z + v.w * v.w;

    #pragma unroll
    for (int o = 16; o; o >>= 1) {
        s  += __shfl_xor_sync(0xffffffffu, s,  o);
        ss += __shfl_xor_sync(0xffffffffu, ss, o);
    }
    __shared__ float rs[8], rss[8];
    if ((t & 31) == 0) { rs[t >> 5] = s; rss[t >> 5] = ss; }
    __syncthreads();
    if (t < 32) {
        float a  = (t < 8) ? rs[t]  : 0.f;
        float bb = (t < 8) ? rss[t] : 0.f;
        #pragma unroll
        for (int o = 4; o; o >>= 1) {
            a  += __shfl_xor_sync(0xffffffffu, a,  o);
            bb += __shfl_xor_sync(0xffffffffu, bb, o);
        }
        if (t == 0) { rs[0] = a; rss[0] = bb; }
    }
    __syncthreads();
    float mean = rs[0] * (1.f / DM);
    float var  = rss[0] * (1.f / DM) - mean * mean;
    float rstd = rsqrtf(var + 1e-5f);

    float4 gv = *(const float4*)(g  + t * 4);
    float4 bv = *(const float4*)(bt + t * 4);
    float o0 = rtf32((v.x - mean) * rstd * gv.x + bv.x);
    float o1 = rtf32((v.y - mean) * rstd * gv.y + bv.y);
    float o2 = rtf32((v.z - mean) * rstd * gv.z + bv.z);
    float o3 = rtf32((v.w - mean) * rstd * gv.w + bv.w);
    int f0 = t * 4;
    float* yp = y + (size_t)row * DM + (f0 & ~7) + ((f0 >> 2) & 1);
    yp[0] = o0; yp[2] = o1; yp[4] = o2; yp[6] = o3;
}

// ---------------------------------------------------------------------------
// Attention: static softmax, balanced task pairs (R13). NEW: warp-uniform
// causal fast paths (skip sel on full tiles, skip everything on fully-masked
// warp-tiles) and no tf32-rounding on P (PV MMA truncates anyway).
// ---------------------------------------------------------------------------
#define ATS 72
#define KVB (64 * ATS)
#define ATTN_SMEM ((4 * KVB + 128 * ATS) * 4)   // 110592 bytes
#define LOG2E 1.4426950408889634f
#define NTASK (32 * (SEQ / 128))                // 512

__global__ __launch_bounds__(256, 2) void attn_mma(
    const float* __restrict__ qkv, float* __restrict__ o)
{
    extern __shared__ float sm[];
    float* KsB = sm;
    float* VsB = sm + 2 * KVB;
    float* Ps  = sm + 4 * KVB;

    int t = threadIdx.x, wid = t >> 5, lane = t & 31;
    int lr = lane >> 2, lc = lane & 3;
    int wr = wid * 16;

    int lv_r = t >> 2, lv_c = (t & 3) * 16;
    uint32_t ks_base = smem_u32(KsB) + (uint32_t)((lv_r * ATS + lv_c) * 4);
    uint32_t vs_base = smem_u32(VsB) + (uint32_t)((lv_r * ATS + lv_c) * 4);

    #pragma unroll 1
    for (int task = 0; task < 2; task++) {
        int tau = (task == 0) ? (int)blockIdx.x : (NTASK - 1 - (int)blockIdx.x);
        int qt  = (SEQ / 128 - 1) - (tau >> 5);
        int bh  = tau & 31;
        int b = bh >> 4, h = bh & 15;
        int q0 = qt * 128;
        float slope = exp2f(-(float)h) * LOG2E;

        const float* base = qkv + (size_t)(b * SEQ) * (3 * DM) + h * DH;

        __syncthreads();   // previous task done with Ps and KV buffers

        // stage Q (x 0.125*log2(e)); verbatim copy preserves permuted layout
        {
            int r = t >> 1, cb = (t & 1) * 32;
            const float* qp = base + (size_t)(q0 + r) * (3 * DM) + cb;
            float* pp = Ps + r * ATS + cb;
            const float qs = 0.125f * LOG2E;
            #pragma unroll
            for (int i = 0; i < 8; i++) {
                float4 v = *(const float4*)(qp + i * 4);
                v.x *= qs; v.y *= qs; v.z *= qs; v.w *= qs;
                *(float4*)(pp + i * 4) = v;
            }
        }
        __syncthreads();
        uint32_t qf[8][4];
        #pragma unroll
        for (int ks = 0; ks < 8; ks++) {
            const float2* p0 = (const float2*)(Ps + (wr + lr) * ATS + ks * 8 + 2 * lc);
            const float2* p1 = (const float2*)(Ps + (wr + lr + 8) * ATS + ks * 8 + 2 * lc);
            float2 v0 = *p0, v1 = *p1;
            qf[ks][0] = __float_as_uint(v0.x);
            qf[ks][2] = __float_as_uint(v0.y);
            qf[ks][1] = __float_as_uint(v1.x);
            qf[ks][3] = __float_as_uint(v1.y);
        }
        __syncthreads();

        float oacc[8][4];
        #pragma unroll
        for (int nt = 0; nt < 8; nt++)
            #pragma unroll
            for (int k = 0; k < 4; k++) oacc[nt][k] = 0.f;
        float l0 = 0.f, l1 = 0.f;
        int r0 = q0 + wr + lr, r1 = r0 + 8;

        int ktmax = 2 * qt + 1;

        // prologue: load kt=0 into buf 0
        {
            const float* kp = base + (size_t)lv_r * (3 * DM) + DM + lv_c;
            #pragma unroll
            for (int i = 0; i < 4; i++) {
                CP16(ks_base + i * 16, kp + i * 4);
                CP16(vs_base + i * 16, kp + DM + i * 4);
            }
            CP_COMMIT();
        }

        for (int kt = 0; kt <= ktmax; kt++) {
            int buf = kt & 1;
            CP_WAIT(0);
            __syncthreads();

            // prefetch kt+1 into buf^1 (overlaps compute below)
            if (kt < ktmax) {
                uint32_t off = (uint32_t)((buf ^ 1) * KVB * 4);
                const float* kp = base + (size_t)((kt + 1) * 64 + lv_r) * (3 * DM) + DM + lv_c;
                #pragma unroll
                for (int i = 0; i < 4; i++) {
                    CP16(ks_base + off + i * 16, kp + i * 4);
                    CP16(vs_base + off + i * 16, kp + DM + i * 4);
                }
                CP_COMMIT();
            }

            int jb = kt * 64;
            // warp-uniform: all 16 rows of this warp below every key -> skip
            if (jb > q0 + wr + 15) continue;

            const float* Kst = KsB + buf * KVB;
            const float* Vst = VsB + buf * KVB;

            // S = Q K^T, column bias -j*slope in accumulator init
            float sacc[8][4];
            #pragma unroll
            for (int nt = 0; nt < 8; nt++) {
                float bj0 = -(float)(jb + nt * 8 + 2 * lc) * slope;
                float bj1 = bj0 - slope;
                sacc[nt][0] = bj0; sacc[nt][1] = bj1;
                sacc[nt][2] = bj0; sacc[nt][3] = bj1;
            }
            #pragma unroll
            for (int ks = 0; ks < 8; ks++) {
                uint32_t bf[8][2];
                #pragma unroll
                for (int nt = 0; nt < 8; nt++) {
                    const float2* p = (const float2*)(Kst + (nt * 8 + lr) * ATS + ks * 8 + 2 * lc);
                    float2 v = *p;
                    bf[nt][0] = __float_as_uint(v.x);
                    bf[nt][1] = __float_as_uint(v.y);
                }
                #pragma unroll
                for (int nt = 0; nt < 8; nt++)
                    mma_tf32(sacc[nt], qf[ks], bf[nt]);
            }

            // exp2, causal zeroing (skipped on warp-uniform full tiles)
            float* pr0 = Ps + (wr + lr) * ATS;
            float* pr1 = pr0 + 8 * ATS;
            bool full = (jb + 63 <= q0 + wr);   // warp-uniform
            if (full) {
                #pragma unroll
                for (int nt = 0; nt < 8; nt++) {
                    float e0 = exp2f(sacc[nt][0]);
                    float e1 = exp2f(sacc[nt][1]);
                    float e2 = exp2f(sacc[nt][2]);
                    float e3 = exp2f(sacc[nt][3]);
                    l0 += e0 + e1;
                    l1 += e2 + e3;
                    *(float2*)(pr0 + nt * 8 + 2 * lc) = make_float2(e0, e1);
                    *(float2*)(pr1 + nt * 8 + 2 * lc) = make_float2(e2, e3);
                }
            } else {
                #pragma unroll
                for (int nt = 0; nt < 8; nt++) {
                    int j0 = jb + nt * 8 + 2 * lc;
                    int j1 = j0 + 1;
                    float e0 = exp2f(sacc[nt][0]);
                    float e1 = exp2f(sacc[nt][1]);
                    float e2 = exp2f(sacc[nt][2]);
                    float e3 = exp2f(sacc[nt][3]);
                    if (j0 > r0) e0 = 0.f;
                    if (j1 > r0) e1 = 0.f;
                    if (j0 > r1) e2 = 0.f;
                    if (j1 > r1) e3 = 0.f;
                    l0 += e0 + e1;
                    l1 += e2 + e3;
                    *(float2*)(pr0 + nt * 8 + 2 * lc) = make_float2(e0, e1);
                    *(float2*)(pr1 + nt * 8 + 2 * lc) = make_float2(e2, e3);
                }
            }
            __syncwarp();

            // O += P V
            #pragma unroll
            for (int ks = 0; ks < 8; ks++) {
                uint32_t pa[4];
                const float* pp = Ps + (wr + lr) * ATS + ks * 8 + lc;
                pa[0] = __float_as_uint(pp[0]);
                pa[1] = __float_as_uint(pp[8 * ATS]);
                pa[2] = __float_as_uint(pp[4]);
                pa[3] = __float_as_uint(pp[8 * ATS + 4]);
                #pragma unroll
                for (int nt = 0; nt < 8; nt++) {
                    uint32_t bv[2];
                    const float* vp = Vst + (ks * 8 + lc) * ATS + nt * 8 + lr;
                    bv[0] = __float_as_uint(vp[0]);
                    bv[1] = __float_as_uint(vp[4 * ATS]);
                    mma_tf32(oacc[nt], pa, bv);
                }
            }
        }

        l0 += __shfl_xor_sync(0xffffffffu, l0, 1);
        l0 += __shfl_xor_sync(0xffffffffu, l0, 2);
        l1 += __shfl_xor_sync(0xffffffffu, l1, 1);
        l1 += __shfl_xor_sync(0xffffffffu, l1, 2);

        float inv0 = 1.f / l0, inv1 = 1.f / l1;
        float* op0 = o + (size_t)(b * SEQ + q0 + wr + lr) * DM + h * DH;
        float* op1 = op0 + (size_t)8 * DM;
        #pragma unroll
        for (int nt = 0; nt < 8; nt++) {
            *(float2*)(op0 + nt * 8 + 2 * lc) =
                make_float2(rtf32(oacc[nt][0] * inv0), rtf32(oacc[nt][1] * inv0));
            *(float2*)(op1 + nt * 8 + 2 * lc) =
                make_float2(rtf32(oacc[nt][2] * inv1), rtf32(oacc[nt][3] * inv1));
        }
    }
}

// ---------------------------------------------------------------------------
// Launch
// ---------------------------------------------------------------------------
extern "C" void kernel_launch(void* const* d_in, const int* in_sizes, int n_in,
                              void* d_out, int out_size)
{
    const float* src   = (const float*)d_in[0];
    const float* ln1_g = (const float*)d_in[1];
    const float* ln1_b = (const float*)d_in[2];
    const float* Wqkv  = (const float*)d_in[3];
    const float* bqkv  = (const float*)d_in[4];
    const float* Wout  = (const float*)d_in[5];
    const float* bout  = (const float*)d_in[6];
    const float* ln2_g = (const float*)d_in[7];
    const float* ln2_b = (const float*)d_in[8];
    const float* W1    = (const float*)d_in[9];
    const float* b1    = (const float*)d_in[10];
    const float* W2    = (const float*)d_in[11];
    const float* b2    = (const float*)d_in[12];
    float* out = (float*)d_out;

    float *h, *qkv, *o, *src2, *f, *ffn, *wq, *wo, *w1, *w2;
    cudaGetSymbolAddress((void**)&h,    g_h);
    cudaGetSymbolAddress((void**)&qkv,  g_qkv);
    cudaGetSymbolAddress((void**)&o,    g_o);
    cudaGetSymbolAddress((void**)&src2, g_src2);
    cudaGetSymbolAddress((void**)&f,    g_f);
    cudaGetSymbolAddress((void**)&ffn,  g_ffn);
    cudaGetSymbolAddress((void**)&wq,   g_wq);
    cudaGetSymbolAddress((void**)&wo,   g_wo);
    cudaGetSymbolAddress((void**)&w1,   g_w1);
    cudaGetSymbolAddress((void**)&w2,   g_w2);

    static bool inited = false;
    static cudaStream_t s2;
    static cudaEvent_t e0, e1, e2, e3;
    if (!inited) {
        cudaStreamCreateWithFlags(&s2, cudaStreamNonBlocking);
        cudaEventCreateWithFlags(&e0, cudaEventDisableTiming);
        cudaEventCreateWithFlags(&e1, cudaEventDisableTiming);
        cudaEventCreateWithFlags(&e2, cudaEventDisableTiming);
        cudaEventCreateWithFlags(&e3, cudaEventDisableTiming);
        cudaFuncSetAttribute(mma_gemm, cudaFuncAttributeMaxDynamicSharedMemorySize, GEMM_SMEM);
        cudaFuncSetAttribute(attn_mma, cudaFuncAttributeMaxDynamicSharedMemorySize, ATTN_SMEM);
        inited = true;
    }

    // fork: wq rounding first (it gates the QKV GEMM)
    cudaEventRecord(e0, 0);
    cudaStreamWaitEvent(s2, e0, 0);
    round_w_kernel<<<(3 * DM * DM / 4 + 255) / 256, 256, 0, s2>>>((const float4*)Wqkv, wq, 3 * DM * DM / 4);
    cudaEventRecord(e1, s2);

    // 1) LN1 -> h (perm); overlaps wq rounding
    ln_kernel<<<MR, 256>>>(src, ln1_g, ln1_b, h);
    cudaEventRecord(e3, 0);   // profiling-index shim: next profiled op = QKV GEMM
    // 2) QKV: perm output features (flags 2|4)
    cudaStreamWaitEvent(0, e1, 0);
    mma_gemm<<<dim3(3 * DM / 128, MR / 128), 256, GEMM_SMEM>>>(
        h, wq, bqkv, nullptr, qkv, 3 * DM, DM, 6);
    // 3) attention -> o (perm via V); 256 uniform CTAs, single wave
    attn_mma<<<NTASK / 2, 256, ATTN_SMEM>>>(qkv, o);

    // remaining weight rounding on s2 (overlaps QKV GEMM + attention)
    round_w_kernel<<<(DM * DM / 4 + 255) / 256, 256, 0, s2>>>((const float4*)Wout, wo, DM * DM / 4);
    round_w_kernel<<<(DFF * DM / 4 + 255) / 256, 256, 0, s2>>>((const float4*)W1, w1, DFF * DM / 4);
    round_w_kernel<<<(DM * DFF / 4 + 255) / 256, 256, 0, s2>>>((const float4*)W2, w2, DM * DFF / 4);
    cudaEventRecord(e2, s2);

    // 4) out-proj: plain output
    cudaStreamWaitEvent(0, e2, 0);
    mma_gemm<<<dim3(DM / 128, MR / 128), 256, GEMM_SMEM>>>(
        o, wo, bout, src, src2, DM, DM, 0);
    // 5) LN2 -> f (perm)
    ln_kernel<<<MR, 256>>>(src2, ln2_g, ln2_b, f);
    // 6) FFN1: relu + round + perm (flags 1|2|4)
    mma_gemm<<<dim3(DFF / 128, MR / 128), 256, GEMM_SMEM>>>(
        f, w1, b1, nullptr, ffn, DFF, DM, 7);
    // 7) FFN2: plain output
    mma_gemm<<<dim3(DM / 128, MR / 128), 256, GEMM_SMEM>>>(
        ffn, w2, b2, src2, out, DM, DFF, 0);
}

// round 15
// speedup vs baseline: 1.5490x; 1.5490x over previous
#include <cuda_runtime.h>
#include <math.h>
#include <stdint.h>

// Problem constants
#define BB   2
#define SEQ  2048
#define DM   1024
#define NH   16
#define DH   64
#define DFF  4096
#define MR   (BB * SEQ)   // 4096 rows

// k-permutation within 8-groups: storage order [0,4,1,5,2,6,3,7]

// ---------------------------------------------------------------------------
// Scratch
// ---------------------------------------------------------------------------
__device__ float g_h   [(size_t)MR * DM];      // LN1 out (perm)
__device__ float g_qkv [(size_t)MR * 3 * DM];  // QKV (features perm)
__device__ float g_o   [(size_t)MR * DM];      // attn out (features perm)
__device__ float g_src2[(size_t)MR * DM];      // residual (plain)
__device__ float g_f   [(size_t)MR * DM];      // LN2 out (perm)
__device__ float g_ffn [(size_t)MR * DFF];     // FFN hidden (perm)
__device__ float g_wq  [(size_t)3 * DM * DM];  // weights: k-perm
__device__ float g_wo  [(size_t)DM * DM];
__device__ float g_w1  [(size_t)DFF * DM];
__device__ float g_w2  [(size_t)DM * DFF];

// ---------------------------------------------------------------------------
// Helpers
// ---------------------------------------------------------------------------
__device__ __forceinline__ uint32_t smem_u32(const void* p) {
    uint32_t a;
    asm("{ .reg .u64 t; cvta.to.shared.u64 t, %1; cvt.u32.u64 %0, t; }" : "=r"(a) : "l"(p));
    return a;
}
__device__ __forceinline__ float rtf32(float x) {
    uint32_t r;
    asm("cvt.rna.tf32.f32 %0, %1;" : "=r"(r) : "f"(x));
    return __uint_as_float(r);
}

#define CP16(dst, src) \
    asm volatile("cp.async.cg.shared.global [%0], [%1], 16;" :: "r"(dst), "l"(src) : "memory")
#define CP_COMMIT()  asm volatile("cp.async.commit_group;" ::: "memory")
#define CP_WAIT(n)   asm volatile("cp.async.wait_group %0;" :: "n"(n) : "memory")

__device__ __forceinline__ void mma_tf32(float* d, const uint32_t* a, const uint32_t* b) {
    asm volatile(
        "mma.sync.aligned.m16n8k8.row.col.f32.tf32.tf32.f32 "
        "{%0,%1,%2,%3}, {%4,%5,%6,%7}, {%8,%9}, {%0,%1,%2,%3};"
        : "+f"(d[0]), "+f"(d[1]), "+f"(d[2]), "+f"(d[3])
        : "r"(a[0]), "r"(a[1]), "r"(a[2]), "r"(a[3]), "r"(b[0]), "r"(b[1]));
}

// ---------------------------------------------------------------------------
// Tensor-core GEMM (R11 frozen): k-permuted operands + XOR swizzle
// (group' = group ^ (row & 3)) -> conflict-free LDS.64 at SMS=32.
// 3 stages, 2 CTAs/SM. CTA 128x128; 8 warps 64x32; BK=32.
// flags: 1 = relu, 2 = tf32-round, 4 = permute output features
// ---------------------------------------------------------------------------
#define ATILE  (128 * 32)
#define STF    (2 * ATILE)
#define STAGES 3
#define GEMM_SMEM (STAGES * STF * 4)   // 98304 bytes

__global__ __launch_bounds__(256, 2) void mma_gemm(
    const float* __restrict__ A, const float* __restrict__ W,
    const float* __restrict__ bias, const float* __restrict__ res,
    float* __restrict__ C, int N, int K, int flags)
{
    extern __shared__ float sm[];

    int t    = threadIdx.x;
    int wid  = t >> 5, lane = t & 31;
    int m0   = blockIdx.y * 128, n0 = blockIdx.x * 128;
    int wm   = (wid >> 2) * 64;
    int wn   = (wid & 3) * 32;
    int lr   = lane >> 2;
    int lc   = lane & 3;
    int jx   = lr & 3;

    int tr  = t >> 3;
    int lg  = (t & 7) >> 1;
    int lw  = (t & 1) * 4;
    const float* Ag = A + (size_t)(m0 + tr) * K + (t & 7) * 4;
    const float* Wg = W + (size_t)(n0 + tr) * K + (t & 7) * 4;
    uint32_t sbase = smem_u32(sm);
    uint32_t sAoff = (uint32_t)((tr * 32 + ((lg ^ (tr & 3)) << 3) + lw) * 4);
    const uint32_t rowStep = 32 * 32 * 4;

    float acc[4][4][4];
    #pragma unroll
    for (int i = 0; i < 4; i++)
        #pragma unroll
        for (int j = 0; j < 4; j++)
            #pragma unroll
            for (int k = 0; k < 4; k++) acc[i][j][k] = 0.f;

    int NK = K >> 5;

    #pragma unroll
    for (int s = 0; s < STAGES - 1; s++) {
        uint32_t sA = sbase + (uint32_t)(s * STF * 4) + sAoff;
        uint32_t sB = sA + (uint32_t)(ATILE * 4);
        const float* Ap = Ag + (size_t)s * 32;
        const float* Wp = Wg + (size_t)s * 32;
        #pragma unroll
        for (int i = 0; i < 4; i++) {
            CP16(sA + i * rowStep, Ap + (size_t)(32 * i) * K);
            CP16(sB + i * rowStep, Wp + (size_t)(32 * i) * K);
        }
        CP_COMMIT();
    }

    for (int kt = 0; kt < NK; kt++) {
        int s = kt % STAGES;
        if (kt + 1 < NK) { CP_WAIT(1); } else { CP_WAIT(0); }
        __syncthreads();

        if (kt + STAGES - 1 < NK) {
            int ls = (kt + STAGES - 1) % STAGES;
            uint32_t sA = sbase + (uint32_t)(ls * STF * 4) + sAoff;
            uint32_t sB = sA + (uint32_t)(ATILE * 4);
            const float* Ap = Ag + (size_t)(kt + STAGES - 1) * 32;
            const float* Wp = Wg + (size_t)(kt + STAGES - 1) * 32;
            #pragma unroll
            for (int i = 0; i < 4; i++) {
                CP16(sA + i * rowStep, Ap + (size_t)(32 * i) * K);
                CP16(sB + i * rowStep, Wp + (size_t)(32 * i) * K);
            }
            CP_COMMIT();
        }

        const float* Ab = sm + s * STF;
        const float* Bb = Ab + ATILE;
        #pragma unroll
        for (int ks = 0; ks < 4; ks++) {
            int kcol = ((ks ^ jx) << 3) + 2 * lc;
            uint32_t a[4][4], b[4][2];
            #pragma unroll
            for (int mt = 0; mt < 4; mt++) {
                const float2* p0 = (const float2*)(Ab + (wm + mt * 16 + lr) * 32 + kcol);
                const float2* p1 = (const float2*)(Ab + (wm + mt * 16 + lr + 8) * 32 + kcol);
                float2 v0 = *p0, v1 = *p1;
                a[mt][0] = __float_as_uint(v0.x);
                a[mt][2] = __float_as_uint(v0.y);
                a[mt][1] = __float_as_uint(v1.x);
                a[mt][3] = __float_as_uint(v1.y);
            }
            #pragma unroll
            for (int nt = 0; nt < 4; nt++) {
                const float2* p = (const float2*)(Bb + (wn + nt * 8 + lr) * 32 + kcol);
                float2 v = *p;
                b[nt][0] = __float_as_uint(v.x);
                b[nt][1] = __float_as_uint(v.y);
            }
            #pragma unroll
            for (int mt = 0; mt < 4; mt++)
                #pragma unroll
                for (int nt = 0; nt < 4; nt++)
                    mma_tf32(acc[mt][nt], a[mt], b[nt]);
        }
    }

    bool do_relu  = (flags & 1) != 0;
    bool do_round = (flags & 2) != 0;
    bool do_perm  = (flags & 4) != 0;
    int f0 = 2 * lc;
    int pos0 = (f0 < 4) ? 2 * f0 : 2 * f0 - 7;
    #pragma unroll
    for (int mt = 0; mt < 4; mt++) {
        int row = m0 + wm + mt * 16 + lr;
        #pragma unroll
        for (int nt = 0; nt < 4; nt++) {
            int colt = n0 + wn + nt * 8 + f0;
            float b0 = __ldg(&bias[colt]), b1 = __ldg(&bias[colt + 1]);
            #pragma unroll
            for (int half = 0; half < 2; half++) {
                int r = row + half * 8;
                float v0 = acc[mt][nt][half * 2 + 0] + b0;
                float v1 = acc[mt][nt][half * 2 + 1] + b1;
                if (res) {
                    const float* rp = res + (size_t)r * N + colt;
                    v0 += rp[0]; v1 += rp[1];
                }
                if (do_relu)  { v0 = fmaxf(v0, 0.f); v1 = fmaxf(v1, 0.f); }
                if (do_round) { v0 = rtf32(v0); v1 = rtf32(v1); }
                if (do_perm) {
                    float* cp = C + (size_t)r * N + n0 + wn + nt * 8;
                    cp[pos0]     = v0;
                    cp[pos0 + 2] = v1;
                } else {
                    *(float2*)(C + (size_t)r * N + colt) = make_float2(v0, v1);
                }
            }
        }
    }
}

// ---------------------------------------------------------------------------
// Round weights to tf32 AND k-permute within 8-groups
// ---------------------------------------------------------------------------
__global__ __launch_bounds__(256) void round_w_kernel(
    const float4* __restrict__ in, float* __restrict__ out, int n4)
{
    int i = blockIdx.x * blockDim.x + threadIdx.x;
    if (i < n4) {
        float4 v = in[i];
        size_t f0 = (size_t)i * 4;
        size_t ob = (f0 & ~(size_t)7) + ((f0 >> 2) & 1);
        out[ob + 0] = rtf32(v.x);
        out[ob + 2] = rtf32(v.y);
        out[ob + 4] = rtf32(v.z);
        out[ob + 6] = rtf32(v.w);
    }
}

// ---------------------------------------------------------------------------
// LayerNorm: tf32-rounded, k-permuted output
// ---------------------------------------------------------------------------
__global__ __launch_bounds__(256) void ln_kernel(
    const float* __restrict__ x, const float* __restrict__ g,
    const float* __restrict__ bt, float* __restrict__ y)
{
    int row = blockIdx.x;
    int t = threadIdx.x;
    const float* xr = x + (size_t)row * DM;

    float4 v = *(const float4*)(xr + t * 4);
    float s  = v.x + v.y + v.z + v.w;
    float ss = v.x * v.x + v.y * v.y + v.z * v.z + v.w * v.w;

    #pragma unroll
    for (int o = 16; o; o >>= 1) {
        s  += __shfl_xor_sync(0xffffffffu, s,  o);
        ss += __shfl_xor_sync(0xffffffffu, ss, o);
    }
    __shared__ float rs[8], rss[8];
    if ((t & 31) == 0) { rs[t >> 5] = s; rss[t >> 5] = ss; }
    __syncthreads();
    if (t < 32) {
        float a  = (t < 8) ? rs[t]  : 0.f;
        float bb = (t < 8) ? rss[t] : 0.f;
        #pragma unroll
        for (int o = 4; o; o >>= 1) {
            a  += __shfl_xor_sync(0xffffffffu, a,  o);
            bb += __shfl_xor_sync(0xffffffffu, bb, o);
        }
        if (t == 0) { rs[0] = a; rss[0] = bb; }
    }
    __syncthreads();
    float mean = rs[0] * (1.f / DM);
    float var  = rss[0] * (1.f / DM) - mean * mean;
    float rstd = rsqrtf(var + 1e-5f);

    float4 gv = *(const float4*)(g  + t * 4);
    float4 bv = *(const float4*)(bt + t * 4);
    float o0 = rtf32((v.x - mean) * rstd * gv.x + bv.x);
    float o1 = rtf32((v.y - mean) * rstd * gv.y + bv.y);
    float o2 = rtf32((v.z - mean) * rstd * gv.z + bv.z);
    float o3 = rtf32((v.w - mean) * rstd * gv.w + bv.w);
    int f0 = t * 4;
    float* yp = y + (size_t)row * DM + (f0 & ~7) + ((f0 >> 2) & 1);
    yp[0] = o0; yp[2] = o1; yp[4] = o2; yp[6] = o3;
}

// ---------------------------------------------------------------------------
// Attention (R13 structure): static softmax, balanced task pairs, single
// uniform loop body (no divergent skips). Only delta vs R13: P stored
// without tf32 rounding (PV MMA truncates anyway).
// ---------------------------------------------------------------------------
#define ATS 72
#define KVB (64 * ATS)
#define ATTN_SMEM ((4 * KVB + 128 * ATS) * 4)   // 110592 bytes
#define LOG2E 1.4426950408889634f
#define NTASK (32 * (SEQ / 128))                // 512

__global__ __launch_bounds__(256, 2) void attn_mma(
    const float* __restrict__ qkv, float* __restrict__ o)
{
    extern __shared__ float sm[];
    float* KsB = sm;
    float* VsB = sm + 2 * KVB;
    float* Ps  = sm + 4 * KVB;

    int t = threadIdx.x, wid = t >> 5, lane = t & 31;
    int lr = lane >> 2, lc = lane & 3;
    int wr = wid * 16;

    int lv_r = t >> 2, lv_c = (t & 3) * 16;
    uint32_t ks_base = smem_u32(KsB) + (uint32_t)((lv_r * ATS + lv_c) * 4);
    uint32_t vs_base = smem_u32(VsB) + (uint32_t)((lv_r * ATS + lv_c) * 4);

    #pragma unroll 1
    for (int task = 0; task < 2; task++) {
        int tau = (task == 0) ? (int)blockIdx.x : (NTASK - 1 - (int)blockIdx.x);
        int qt  = (SEQ / 128 - 1) - (tau >> 5);
        int bh  = tau & 31;
        int b = bh >> 4, h = bh & 15;
        int q0 = qt * 128;
        float slope = exp2f(-(float)h) * LOG2E;

        const float* base = qkv + (size_t)(b * SEQ) * (3 * DM) + h * DH;

        __syncthreads();   // previous task done with Ps and KV buffers

        // stage Q (x 0.125*log2(e)); verbatim copy preserves permuted layout
        {
            int r = t >> 1, cb = (t & 1) * 32;
            const float* qp = base + (size_t)(q0 + r) * (3 * DM) + cb;
            float* pp = Ps + r * ATS + cb;
            const float qs = 0.125f * LOG2E;
            #pragma unroll
            for (int i = 0; i < 8; i++) {
                float4 v = *(const float4*)(qp + i * 4);
                v.x *= qs; v.y *= qs; v.z *= qs; v.w *= qs;
                *(float4*)(pp + i * 4) = v;
            }
        }
        __syncthreads();
        uint32_t qf[8][4];
        #pragma unroll
        for (int ks = 0; ks < 8; ks++) {
            const float2* p0 = (const float2*)(Ps + (wr + lr) * ATS + ks * 8 + 2 * lc);
            const float2* p1 = (const float2*)(Ps + (wr + lr + 8) * ATS + ks * 8 + 2 * lc);
            float2 v0 = *p0, v1 = *p1;
            qf[ks][0] = __float_as_uint(v0.x);
            qf[ks][2] = __float_as_uint(v0.y);
            qf[ks][1] = __float_as_uint(v1.x);
            qf[ks][3] = __float_as_uint(v1.y);
        }
        __syncthreads();

        float oacc[8][4];
        #pragma unroll
        for (int nt = 0; nt < 8; nt++)
            #pragma unroll
            for (int k = 0; k < 4; k++) oacc[nt][k] = 0.f;
        float l0 = 0.f, l1 = 0.f;
        int r0 = q0 + wr + lr, r1 = r0 + 8;

        int ktmax = 2 * qt + 1;

        // prologue: load kt=0 into buf 0
        {
            const float* kp = base + (size_t)lv_r * (3 * DM) + DM + lv_c;
            #pragma unroll
            for (int i = 0; i < 4; i++) {
                CP16(ks_base + i * 16, kp + i * 4);
                CP16(vs_base + i * 16, kp + DM + i * 4);
            }
            CP_COMMIT();
        }

        for (int kt = 0; kt <= ktmax; kt++) {
            int buf = kt & 1;
            CP_WAIT(0);
            __syncthreads();

            // prefetch kt+1 into buf^1 (overlaps compute below)
            if (kt < ktmax) {
                uint32_t off = (uint32_t)((buf ^ 1) * KVB * 4);
                const float* kp = base + (size_t)((kt + 1) * 64 + lv_r) * (3 * DM) + DM + lv_c;
                #pragma unroll
                for (int i = 0; i < 4; i++) {
                    CP16(ks_base + off + i * 16, kp + i * 4);
                    CP16(vs_base + off + i * 16, kp + DM + i * 4);
                }
                CP_COMMIT();
            }

            const float* Kst = KsB + buf * KVB;
            const float* Vst = VsB + buf * KVB;

            int jb = kt * 64;

            // S = Q K^T, column bias -j*slope in accumulator init
            float sacc[8][4];
            #pragma unroll
            for (int nt = 0; nt < 8; nt++) {
                float bj0 = -(float)(jb + nt * 8 + 2 * lc) * slope;
                float bj1 = bj0 - slope;
                sacc[nt][0] = bj0; sacc[nt][1] = bj1;
                sacc[nt][2] = bj0; sacc[nt][3] = bj1;
            }
            #pragma unroll
            for (int ks = 0; ks < 8; ks++) {
                uint32_t bf[8][2];
                #pragma unroll
                for (int nt = 0; nt < 8; nt++) {
                    const float2* p = (const float2*)(Kst + (nt * 8 + lr) * ATS + ks * 8 + 2 * lc);
                    float2 v = *p;
                    bf[nt][0] = __float_as_uint(v.x);
                    bf[nt][1] = __float_as_uint(v.y);
                }
                #pragma unroll
                for (int nt = 0; nt < 8; nt++)
                    mma_tf32(sacc[nt], qf[ks], bf[nt]);
            }

            // exp2, causal zeroing, local sums, store P (no tf32 rounding)
            float* pr0 = Ps + (wr + lr) * ATS;
            float* pr1 = pr0 + 8 * ATS;
            #pragma unroll
            for (int nt = 0; nt < 8; nt++) {
                int j0 = jb + nt * 8 + 2 * lc;
                int j1 = j0 + 1;
                float e0 = exp2f(sacc[nt][0]);
                float e1 = exp2f(sacc[nt][1]);
                float e2 = exp2f(sacc[nt][2]);
                float e3 = exp2f(sacc[nt][3]);
                if (j0 > r0) e0 = 0.f;
                if (j1 > r0) e1 = 0.f;
                if (j0 > r1) e2 = 0.f;
                if (j1 > r1) e3 = 0.f;
                l0 += e0 + e1;
                l1 += e2 + e3;
                *(float2*)(pr0 + nt * 8 + 2 * lc) = make_float2(e0, e1);
                *(float2*)(pr1 + nt * 8 + 2 * lc) = make_float2(e2, e3);
            }
            __syncwarp();

            // O += P V
            #pragma unroll
            for (int ks = 0; ks < 8; ks++) {
                uint32_t pa[4];
                const float* pp = Ps + (wr + lr) * ATS + ks * 8 + lc;
                pa[0] = __float_as_uint(pp[0]);
                pa[1] = __float_as_uint(pp[8 * ATS]);
                pa[2] = __float_as_uint(pp[4]);
                pa[3] = __float_as_uint(pp[8 * ATS + 4]);
                #pragma unroll
                for (int nt = 0; nt < 8; nt++) {
                    uint32_t bv[2];
                    const float* vp = Vst + (ks * 8 + lc) * ATS + nt * 8 + lr;
                    bv[0] = __float_as_uint(vp[0]);
                    bv[1] = __float_as_uint(vp[4 * ATS]);
                    mma_tf32(oacc[nt], pa, bv);
                }
            }
        }

        l0 += __shfl_xor_sync(0xffffffffu, l0, 1);
        l0 += __shfl_xor_sync(0xffffffffu, l0, 2);
        l1 += __shfl_xor_sync(0xffffffffu, l1, 1);
        l1 += __shfl_xor_sync(0xffffffffu, l1, 2);

        float inv0 = 1.f / l0, inv1 = 1.f / l1;
        float* op0 = o + (size_t)(b * SEQ + q0 + wr + lr) * DM + h * DH;
        float* op1 = op0 + (size_t)8 * DM;
        #pragma unroll
        for (int nt = 0; nt < 8; nt++) {
            *(float2*)(op0 + nt * 8 + 2 * lc) =
                make_float2(rtf32(oacc[nt][0] * inv0), rtf32(oacc[nt][1] * inv0));
            *(float2*)(op1 + nt * 8 + 2 * lc) =
                make_float2(rtf32(oacc[nt][2] * inv1), rtf32(oacc[nt][3] * inv1));
        }
    }
}

// ---------------------------------------------------------------------------
// Launch
// ---------------------------------------------------------------------------
extern "C" void kernel_launch(void* const* d_in, const int* in_sizes, int n_in,
                              void* d_out, int out_size)
{
    const float* src   = (const float*)d_in[0];
    const float* ln1_g = (const float*)d_in[1];
    const float* ln1_b = (const float*)d_in[2];
    const float* Wqkv  = (const float*)d_in[3];
    const float* bqkv  = (const float*)d_in[4];
    const float* Wout  = (const float*)d_in[5];
    const float* bout  = (const float*)d_in[6];
    const float* ln2_g = (const float*)d_in[7];
    const float* ln2_b = (const float*)d_in[8];
    const float* W1    = (const float*)d_in[9];
    const float* b1    = (const float*)d_in[10];
    const float* W2    = (const float*)d_in[11];
    const float* b2    = (const float*)d_in[12];
    float* out = (float*)d_out;

    float *h, *qkv, *o, *src2, *f, *ffn, *wq, *wo, *w1, *w2;
    cudaGetSymbolAddress((void**)&h,    g_h);
    cudaGetSymbolAddress((void**)&qkv,  g_qkv);
    cudaGetSymbolAddress((void**)&o,    g_o);
    cudaGetSymbolAddress((void**)&src2, g_src2);
    cudaGetSymbolAddress((void**)&f,    g_f);
    cudaGetSymbolAddress((void**)&ffn,  g_ffn);
    cudaGetSymbolAddress((void**)&wq,   g_wq);
    cudaGetSymbolAddress((void**)&wo,   g_wo);
    cudaGetSymbolAddress((void**)&w1,   g_w1);
    cudaGetSymbolAddress((void**)&w2,   g_w2);

    static bool inited = false;
    static cudaStream_t s2;
    static cudaEvent_t e0, e1, e2, e3;
    if (!inited) {
        cudaStreamCreateWithFlags(&s2, cudaStreamNonBlocking);
        cudaEventCreateWithFlags(&e0, cudaEventDisableTiming);
        cudaEventCreateWithFlags(&e1, cudaEventDisableTiming);
        cudaEventCreateWithFlags(&e2, cudaEventDisableTiming);
        cudaEventCreateWithFlags(&e3, cudaEventDisableTiming);
        cudaFuncSetAttribute(mma_gemm, cudaFuncAttributeMaxDynamicSharedMemorySize, GEMM_SMEM);
        cudaFuncSetAttribute(attn_mma, cudaFuncAttributeMaxDynamicSharedMemorySize, ATTN_SMEM);
        inited = true;
    }

    // fork: wq rounding first (it gates the QKV GEMM)
    cudaEventRecord(e0, 0);
    cudaStreamWaitEvent(s2, e0, 0);
    round_w_kernel<<<(3 * DM * DM / 4 + 255) / 256, 256, 0, s2>>>((const float4*)Wqkv, wq, 3 * DM * DM / 4);
    cudaEventRecord(e1, s2);

    // 1) LN1 -> h (perm); overlaps wq rounding
    ln_kernel<<<MR, 256>>>(src, ln1_g, ln1_b, h);
    cudaEventRecord(e3, 0);   // profiling-index shim: next profiled op = QKV GEMM
    // 2) QKV: perm output features (flags 2|4)
    cudaStreamWaitEvent(0, e1, 0);
    mma_gemm<<<dim3(3 * DM / 128, MR / 128), 256, GEMM_SMEM>>>(
        h, wq, bqkv, nullptr, qkv, 3 * DM, DM, 6);
    // 3) attention -> o (perm via V); 256 uniform CTAs, single wave
    attn_mma<<<NTASK / 2, 256, ATTN_SMEM>>>(qkv, o);

    // remaining weight rounding on s2 (overlaps QKV GEMM + attention)
    round_w_kernel<<<(DM * DM / 4 + 255) / 256, 256, 0, s2>>>((const float4*)Wout, wo, DM * DM / 4);
    round_w_kernel<<<(DFF * DM / 4 + 255) / 256, 256, 0, s2>>>((const float4*)W1, w1, DFF * DM / 4);
    round_w_kernel<<<(DM * DFF / 4 + 255) / 256, 256, 0, s2>>>((const float4*)W2, w2, DM * DFF / 4);
    cudaEventRecord(e2, s2);

    // 4) out-proj: plain output
    cudaStreamWaitEvent(0, e2, 0);
    mma_gemm<<<dim3(DM / 128, MR / 128), 256, GEMM_SMEM>>>(
        o, wo, bout, src, src2, DM, DM, 0);
    // 5) LN2 -> f (perm)
    ln_kernel<<<MR, 256>>>(src2, ln2_g, ln2_b, f);
    // 6) FFN1: relu + round + perm (flags 1|2|4)
    mma_gemm<<<dim3(DFF / 128, MR / 128), 256, GEMM_SMEM>>>(
        f, w1, b1, nullptr, ffn, DFF, DM, 7);
    // 7) FFN2: plain output
    mma_gemm<<<dim3(DM / 128, MR / 128), 256, GEMM_SMEM>>>(
        ffn, w2, b2, src2, out, DM, DFF, 0);
}

// round 16
// speedup vs baseline: 1.5820x; 1.0213x over previous
#include <cuda_runtime.h>
#include <math.h>
#include <stdint.h>

// Problem constants
#define BB   2
#define SEQ  2048
#define DM   1024
#define NH   16
#define DH   64
#define DFF  4096
#define MR   (BB * SEQ)   // 4096 rows

// k-permutation within 8-groups: storage order [0,4,1,5,2,6,3,7]

// ---------------------------------------------------------------------------
// Scratch
// ---------------------------------------------------------------------------
__device__ float g_h   [(size_t)MR * DM];      // LN1 out (perm)
__device__ float g_qkv [(size_t)MR * 3 * DM];  // QKV (features perm)
__device__ float g_o   [(size_t)MR * DM];      // attn out (features perm)
__device__ float g_src2[(size_t)MR * DM];      // residual (plain)
__device__ float g_f   [(size_t)MR * DM];      // LN2 out (perm)
__device__ float g_ffn [(size_t)MR * DFF];     // FFN hidden (perm)
__device__ float g_wq  [(size_t)3 * DM * DM];  // weights: k-perm
__device__ float g_wo  [(size_t)DM * DM];
__device__ float g_w1  [(size_t)DFF * DM];
__device__ float g_w2  [(size_t)DM * DFF];

// ---------------------------------------------------------------------------
// Helpers
// ---------------------------------------------------------------------------
__device__ __forceinline__ uint32_t smem_u32(const void* p) {
    uint32_t a;
    asm("{ .reg .u64 t; cvta.to.shared.u64 t, %1; cvt.u32.u64 %0, t; }" : "=r"(a) : "l"(p));
    return a;
}
__device__ __forceinline__ float rtf32(float x) {
    uint32_t r;
    asm("cvt.rna.tf32.f32 %0, %1;" : "=r"(r) : "f"(x));
    return __uint_as_float(r);
}

#define CP16(dst, src) \
    asm volatile("cp.async.cg.shared.global [%0], [%1], 16;" :: "r"(dst), "l"(src) : "memory")
#define CP_COMMIT()  asm volatile("cp.async.commit_group;" ::: "memory")
#define CP_WAIT(n)   asm volatile("cp.async.wait_group %0;" :: "n"(n) : "memory")

__device__ __forceinline__ void mma_tf32(float* d, const uint32_t* a, const uint32_t* b) {
    asm volatile(
        "mma.sync.aligned.m16n8k8.row.col.f32.tf32.tf32.f32 "
        "{%0,%1,%2,%3}, {%4,%5,%6,%7}, {%8,%9}, {%0,%1,%2,%3};"
        : "+f"(d[0]), "+f"(d[1]), "+f"(d[2]), "+f"(d[3])
        : "r"(a[0]), "r"(a[1]), "r"(a[2]), "r"(a[3]), "r"(b[0]), "r"(b[1]));
}
__device__ __forceinline__ void mma_tf32_f(float* d, float a0, float a1, float a2, float a3,
                                           float b0, float b1) {
    asm volatile(
        "mma.sync.aligned.m16n8k8.row.col.f32.tf32.tf32.f32 "
        "{%0,%1,%2,%3}, {%4,%5,%6,%7}, {%8,%9}, {%0,%1,%2,%3};"
        : "+f"(d[0]), "+f"(d[1]), "+f"(d[2]), "+f"(d[3])
        : "r"(__float_as_uint(a0)), "r"(__float_as_uint(a1)),
          "r"(__float_as_uint(a2)), "r"(__float_as_uint(a3)),
          "r"(__float_as_uint(b0)), "r"(__float_as_uint(b1)));
}

// ---------------------------------------------------------------------------
// Tensor-core GEMM (R11 frozen): k-permuted operands + XOR swizzle
// (group' = group ^ (row & 3)) -> conflict-free LDS.64 at SMS=32.
// 3 stages, 2 CTAs/SM. CTA 128x128; 8 warps 64x32; BK=32.
// flags: 1 = relu, 2 = tf32-round, 4 = permute output features
// ---------------------------------------------------------------------------
#define ATILE  (128 * 32)
#define STF    (2 * ATILE)
#define STAGES 3
#define GEMM_SMEM (STAGES * STF * 4)   // 98304 bytes

__global__ __launch_bounds__(256, 2) void mma_gemm(
    const float* __restrict__ A, const float* __restrict__ W,
    const float* __restrict__ bias, const float* __restrict__ res,
    float* __restrict__ C, int N, int K, int flags)
{
    extern __shared__ float sm[];

    int t    = threadIdx.x;
    int wid  = t >> 5, lane = t & 31;
    int m0   = blockIdx.y * 128, n0 = blockIdx.x * 128;
    int wm   = (wid >> 2) * 64;
    int wn   = (wid & 3) * 32;
    int lr   = lane >> 2;
    int lc   = lane & 3;
    int jx   = lr & 3;

    int tr  = t >> 3;
    int lg  = (t & 7) >> 1;
    int lw  = (t & 1) * 4;
    const float* Ag = A + (size_t)(m0 + tr) * K + (t & 7) * 4;
    const float* Wg = W + (size_t)(n0 + tr) * K + (t & 7) * 4;
    uint32_t sbase = smem_u32(sm);
    uint32_t sAoff = (uint32_t)((tr * 32 + ((lg ^ (tr & 3)) << 3) + lw) * 4);
    const uint32_t rowStep = 32 * 32 * 4;

    float acc[4][4][4];
    #pragma unroll
    for (int i = 0; i < 4; i++)
        #pragma unroll
        for (int j = 0; j < 4; j++)
            #pragma unroll
            for (int k = 0; k < 4; k++) acc[i][j][k] = 0.f;

    int NK = K >> 5;

    #pragma unroll
    for (int s = 0; s < STAGES - 1; s++) {
        uint32_t sA = sbase + (uint32_t)(s * STF * 4) + sAoff;
        uint32_t sB = sA + (uint32_t)(ATILE * 4);
        const float* Ap = Ag + (size_t)s * 32;
        const float* Wp = Wg + (size_t)s * 32;
        #pragma unroll
        for (int i = 0; i < 4; i++) {
            CP16(sA + i * rowStep, Ap + (size_t)(32 * i) * K);
            CP16(sB + i * rowStep, Wp + (size_t)(32 * i) * K);
        }
        CP_COMMIT();
    }

    for (int kt = 0; kt < NK; kt++) {
        int s = kt % STAGES;
        if (kt + 1 < NK) { CP_WAIT(1); } else { CP_WAIT(0); }
        __syncthreads();

        if (kt + STAGES - 1 < NK) {
            int ls = (kt + STAGES - 1) % STAGES;
            uint32_t sA = sbase + (uint32_t)(ls * STF * 4) + sAoff;
            uint32_t sB = sA + (uint32_t)(ATILE * 4);
            const float* Ap = Ag + (size_t)(kt + STAGES - 1) * 32;
            const float* Wp = Wg + (size_t)(kt + STAGES - 1) * 32;
            #pragma unroll
            for (int i = 0; i < 4; i++) {
                CP16(sA + i * rowStep, Ap + (size_t)(32 * i) * K);
                CP16(sB + i * rowStep, Wp + (size_t)(32 * i) * K);
            }
            CP_COMMIT();
        }

        const float* Ab = sm + s * STF;
        const float* Bb = Ab + ATILE;
        #pragma unroll
        for (int ks = 0; ks < 4; ks++) {
            int kcol = ((ks ^ jx) << 3) + 2 * lc;
            uint32_t a[4][4], b[4][2];
            #pragma unroll
            for (int mt = 0; mt < 4; mt++) {
                const float2* p0 = (const float2*)(Ab + (wm + mt * 16 + lr) * 32 + kcol);
                const float2* p1 = (const float2*)(Ab + (wm + mt * 16 + lr + 8) * 32 + kcol);
                float2 v0 = *p0, v1 = *p1;
                a[mt][0] = __float_as_uint(v0.x);
                a[mt][2] = __float_as_uint(v0.y);
                a[mt][1] = __float_as_uint(v1.x);
                a[mt][3] = __float_as_uint(v1.y);
            }
            #pragma unroll
            for (int nt = 0; nt < 4; nt++) {
                const float2* p = (const float2*)(Bb + (wn + nt * 8 + lr) * 32 + kcol);
                float2 v = *p;
                b[nt][0] = __float_as_uint(v.x);
                b[nt][1] = __float_as_uint(v.y);
            }
            #pragma unroll
            for (int mt = 0; mt < 4; mt++)
                #pragma unroll
                for (int nt = 0; nt < 4; nt++)
                    mma_tf32(acc[mt][nt], a[mt], b[nt]);
        }
    }

    bool do_relu  = (flags & 1) != 0;
    bool do_round = (flags & 2) != 0;
    bool do_perm  = (flags & 4) != 0;
    int f0 = 2 * lc;
    int pos0 = (f0 < 4) ? 2 * f0 : 2 * f0 - 7;
    #pragma unroll
    for (int mt = 0; mt < 4; mt++) {
        int row = m0 + wm + mt * 16 + lr;
        #pragma unroll
        for (int nt = 0; nt < 4; nt++) {
            int colt = n0 + wn + nt * 8 + f0;
            float b0 = __ldg(&bias[colt]), b1 = __ldg(&bias[colt + 1]);
            #pragma unroll
            for (int half = 0; half < 2; half++) {
                int r = row + half * 8;
                float v0 = acc[mt][nt][half * 2 + 0] + b0;
                float v1 = acc[mt][nt][half * 2 + 1] + b1;
                if (res) {
                    const float* rp = res + (size_t)r * N + colt;
                    v0 += rp[0]; v1 += rp[1];
                }
                if (do_relu)  { v0 = fmaxf(v0, 0.f); v1 = fmaxf(v1, 0.f); }
                if (do_round) { v0 = rtf32(v0); v1 = rtf32(v1); }
                if (do_perm) {
                    float* cp = C + (size_t)r * N + n0 + wn + nt * 8;
                    cp[pos0]     = v0;
                    cp[pos0 + 2] = v1;
                } else {
                    *(float2*)(C + (size_t)r * N + colt) = make_float2(v0, v1);
                }
            }
        }
    }
}

// ---------------------------------------------------------------------------
// Round weights to tf32 AND k-permute within 8-groups
// ---------------------------------------------------------------------------
__global__ __launch_bounds__(256) void round_w_kernel(
    const float4* __restrict__ in, float* __restrict__ out, int n4)
{
    int i = blockIdx.x * blockDim.x + threadIdx.x;
    if (i < n4) {
        float4 v = in[i];
        size_t f0 = (size_t)i * 4;
        size_t ob = (f0 & ~(size_t)7) + ((f0 >> 2) & 1);
        out[ob + 0] = rtf32(v.x);
        out[ob + 2] = rtf32(v.y);
        out[ob + 4] = rtf32(v.z);
        out[ob + 6] = rtf32(v.w);
    }
}

// ---------------------------------------------------------------------------
// LayerNorm: tf32-rounded, k-permuted output
// ---------------------------------------------------------------------------
__global__ __launch_bounds__(256) void ln_kernel(
    const float* __restrict__ x, const float* __restrict__ g,
    const float* __restrict__ bt, float* __restrict__ y)
{
    int row = blockIdx.x;
    int t = threadIdx.x;
    const float* xr = x + (size_t)row * DM;

    float4 v = *(const float4*)(xr + t * 4);
    float s  = v.x + v.y + v.z + v.w;
    float ss = v.x * v.x + v.y * v.y + v.z * v.z + v.w * v.w;

    #pragma unroll
    for (int o = 16; o; o >>= 1) {
        s  += __shfl_xor_sync(0xffffffffu, s,  o);
        ss += __shfl_xor_sync(0xffffffffu, ss, o);
    }
    __shared__ float rs[8], rss[8];
    if ((t & 31) == 0) { rs[t >> 5] = s; rss[t >> 5] = ss; }
    __syncthreads();
    if (t < 32) {
        float a  = (t < 8) ? rs[t]  : 0.f;
        float bb = (t < 8) ? rss[t] : 0.f;
        #pragma unroll
        for (int o = 4; o; o >>= 1) {
            a  += __shfl_xor_sync(0xffffffffu, a,  o);
            bb += __shfl_xor_sync(0xffffffffu, bb, o);
        }
        if (t == 0) { rs[0] = a; rss[0] = bb; }
    }
    __syncthreads();
    float mean = rs[0] * (1.f / DM);
    float var  = rss[0] * (1.f / DM) - mean * mean;
    float rstd = rsqrtf(var + 1e-5f);

    float4 gv = *(const float4*)(g  + t * 4);
    float4 bv = *(const float4*)(bt + t * 4);
    float o0 = rtf32((v.x - mean) * rstd * gv.x + bv.x);
    float o1 = rtf32((v.y - mean) * rstd * gv.y + bv.y);
    float o2 = rtf32((v.z - mean) * rstd * gv.z + bv.z);
    float o3 = rtf32((v.w - mean) * rstd * gv.w + bv.w);
    int f0 = t * 4;
    float* yp = y + (size_t)row * DM + (f0 & ~7) + ((f0 >> 2) & 1);
    yp[0] = o0; yp[2] = o1; yp[4] = o2; yp[6] = o3;
}

// ---------------------------------------------------------------------------
// Attention (R15 trunk + P-in-registers):
//  - P never touches smem: PV A-operand = exp(sacc) with components
//    reordered (c0,c2,c1,c3); the matching key permutation is absorbed by
//    reading V rows (ks*8+2lc, ks*8+2lc+1).
//  - V stored at stride 68 (banks 8lc+lr(+4): conflict-free for the new
//    row pattern); K/Q keep proven stride 72.
// ---------------------------------------------------------------------------
#define ATS  72                         // K tile / Q stage stride
#define ATSV 68                         // V tile stride
#define KVBK (64 * ATS)
#define KVBV (64 * ATSV)
#define ATTN_SMEM ((2 * KVBK + 2 * KVBV + 128 * ATS) * 4)   // 108544 bytes
#define LOG2E 1.4426950408889634f
#define NTASK (32 * (SEQ / 128))        // 512

__global__ __launch_bounds__(256, 2) void attn_mma(
    const float* __restrict__ qkv, float* __restrict__ o)
{
    extern __shared__ float sm[];
    float* KsB = sm;                    // [2][64][72]
    float* VsB = sm + 2 * KVBK;         // [2][64][68]
    float* Ps  = sm + 2 * KVBK + 2 * KVBV;   // [128][72] (Q stage only)

    int t = threadIdx.x, wid = t >> 5, lane = t & 31;
    int lr = lane >> 2, lc = lane & 3;
    int wr = wid * 16;

    int lv_r = t >> 2, lv_c = (t & 3) * 16;
    uint32_t ks_base = smem_u32(KsB) + (uint32_t)((lv_r * ATS  + lv_c) * 4);
    uint32_t vs_base = smem_u32(VsB) + (uint32_t)((lv_r * ATSV + lv_c) * 4);

    #pragma unroll 1
    for (int task = 0; task < 2; task++) {
        int tau = (task == 0) ? (int)blockIdx.x : (NTASK - 1 - (int)blockIdx.x);
        int qt  = (SEQ / 128 - 1) - (tau >> 5);
        int bh  = tau & 31;
        int b = bh >> 4, h = bh & 15;
        int q0 = qt * 128;
        float slope = exp2f(-(float)h) * LOG2E;

        const float* base = qkv + (size_t)(b * SEQ) * (3 * DM) + h * DH;

        __syncthreads();   // previous task done with Ps and KV buffers

        // stage Q (x 0.125*log2(e)); verbatim copy preserves permuted layout
        {
            int r = t >> 1, cb = (t & 1) * 32;
            const float* qp = base + (size_t)(q0 + r) * (3 * DM) + cb;
            float* pp = Ps + r * ATS + cb;
            const float qs = 0.125f * LOG2E;
            #pragma unroll
            for (int i = 0; i < 8; i++) {
                float4 v = *(const float4*)(qp + i * 4);
                v.x *= qs; v.y *= qs; v.z *= qs; v.w *= qs;
                *(float4*)(pp + i * 4) = v;
            }
        }
        __syncthreads();
        uint32_t qf[8][4];
        #pragma unroll
        for (int ks = 0; ks < 8; ks++) {
            const float2* p0 = (const float2*)(Ps + (wr + lr) * ATS + ks * 8 + 2 * lc);
            const float2* p1 = (const float2*)(Ps + (wr + lr + 8) * ATS + ks * 8 + 2 * lc);
            float2 v0 = *p0, v1 = *p1;
            qf[ks][0] = __float_as_uint(v0.x);
            qf[ks][2] = __float_as_uint(v0.y);
            qf[ks][1] = __float_as_uint(v1.x);
            qf[ks][3] = __float_as_uint(v1.y);
        }

        float oacc[8][4];
        #pragma unroll
        for (int nt = 0; nt < 8; nt++)
            #pragma unroll
            for (int k = 0; k < 4; k++) oacc[nt][k] = 0.f;
        float l0 = 0.f, l1 = 0.f;
        int r0 = q0 + wr + lr, r1 = r0 + 8;

        int ktmax = 2 * qt + 1;

        // prologue: load kt=0 into buf 0
        {
            const float* kp = base + (size_t)lv_r * (3 * DM) + DM + lv_c;
            #pragma unroll
            for (int i = 0; i < 4; i++) {
                CP16(ks_base + i * 16, kp + i * 4);
                CP16(vs_base + i * 16, kp + DM + i * 4);
            }
            CP_COMMIT();
        }

        for (int kt = 0; kt <= ktmax; kt++) {
            int buf = kt & 1;
            CP_WAIT(0);
            __syncthreads();

            // prefetch kt+1 into buf^1 (overlaps compute below)
            if (kt < ktmax) {
                uint32_t offK = (uint32_t)((buf ^ 1) * KVBK * 4);
                uint32_t offV = (uint32_t)((buf ^ 1) * KVBV * 4);
                const float* kp = base + (size_t)((kt + 1) * 64 + lv_r) * (3 * DM) + DM + lv_c;
                #pragma unroll
                for (int i = 0; i < 4; i++) {
                    CP16(ks_base + offK + i * 16, kp + i * 4);
                    CP16(vs_base + offV + i * 16, kp + DM + i * 4);
                }
                CP_COMMIT();
            }

            const float* Kst = KsB + buf * KVBK;
            const float* Vst = VsB + buf * KVBV;

            int jb = kt * 64;

            // S = Q K^T, column bias -j*slope in accumulator init
            float sacc[8][4];
            #pragma unroll
            for (int nt = 0; nt < 8; nt++) {
                float bj0 = -(float)(jb + nt * 8 + 2 * lc) * slope;
                float bj1 = bj0 - slope;
                sacc[nt][0] = bj0; sacc[nt][1] = bj1;
                sacc[nt][2] = bj0; sacc[nt][3] = bj1;
            }
            #pragma unroll
            for (int ks = 0; ks < 8; ks++) {
                uint32_t bf[8][2];
                #pragma unroll
                for (int nt = 0; nt < 8; nt++) {
                    const float2* p = (const float2*)(Kst + (nt * 8 + lr) * ATS + ks * 8 + 2 * lc);
                    float2 v = *p;
                    bf[nt][0] = __float_as_uint(v.x);
                    bf[nt][1] = __float_as_uint(v.y);
                }
                #pragma unroll
                for (int nt = 0; nt < 8; nt++)
                    mma_tf32(sacc[nt], qf[ks], bf[nt]);
            }

            // exp2, causal zeroing, local sums — P stays in sacc registers
            #pragma unroll
            for (int nt = 0; nt < 8; nt++) {
                int j0 = jb + nt * 8 + 2 * lc;
                int j1 = j0 + 1;
                float e0 = exp2f(sacc[nt][0]);
                float e1 = exp2f(sacc[nt][1]);
                float e2 = exp2f(sacc[nt][2]);
                float e3 = exp2f(sacc[nt][3]);
                if (j0 > r0) e0 = 0.f;
                if (j1 > r0) e1 = 0.f;
                if (j0 > r1) e2 = 0.f;
                if (j1 > r1) e3 = 0.f;
                l0 += e0 + e1;
                l1 += e2 + e3;
                sacc[nt][0] = e0; sacc[nt][1] = e1;
                sacc[nt][2] = e2; sacc[nt][3] = e3;
            }

            // O += P V: A-frag = (c0,c2,c1,c3) of sacc[ks]; matching key
            // permutation absorbed by V rows (ks*8+2lc, ks*8+2lc+1).
            #pragma unroll
            for (int ks = 0; ks < 8; ks++) {
                const float* vp = Vst + (ks * 8 + 2 * lc) * ATSV;
                #pragma unroll
                for (int nt = 0; nt < 8; nt++) {
                    const float* vq = vp + nt * 8 + lr;
                    mma_tf32_f(oacc[nt],
                               sacc[ks][0], sacc[ks][2], sacc[ks][1], sacc[ks][3],
                               vq[0], vq[ATSV]);
                }
            }
        }

        l0 += __shfl_xor_sync(0xffffffffu, l0, 1);
        l0 += __shfl_xor_sync(0xffffffffu, l0, 2);
        l1 += __shfl_xor_sync(0xffffffffu, l1, 1);
        l1 += __shfl_xor_sync(0xffffffffu, l1, 2);

        float inv0 = 1.f / l0, inv1 = 1.f / l1;
        float* op0 = o + (size_t)(b * SEQ + q0 + wr + lr) * DM + h * DH;
        float* op1 = op0 + (size_t)8 * DM;
        #pragma unroll
        for (int nt = 0; nt < 8; nt++) {
            *(float2*)(op0 + nt * 8 + 2 * lc) =
                make_float2(rtf32(oacc[nt][0] * inv0), rtf32(oacc[nt][1] * inv0));
            *(float2*)(op1 + nt * 8 + 2 * lc) =
                make_float2(rtf32(oacc[nt][2] * inv1), rtf32(oacc[nt][3] * inv1));
        }
    }
}

// ---------------------------------------------------------------------------
// Launch
// ---------------------------------------------------------------------------
extern "C" void kernel_launch(void* const* d_in, const int* in_sizes, int n_in,
                              void* d_out, int out_size)
{
    const float* src   = (const float*)d_in[0];
    const float* ln1_g = (const float*)d_in[1];
    const float* ln1_b = (const float*)d_in[2];
    const float* Wqkv  = (const float*)d_in[3];
    const float* bqkv  = (const float*)d_in[4];
    const float* Wout  = (const float*)d_in[5];
    const float* bout  = (const float*)d_in[6];
    const float* ln2_g = (const float*)d_in[7];
    const float* ln2_b = (const float*)d_in[8];
    const float* W1    = (const float*)d_in[9];
    const float* b1    = (const float*)d_in[10];
    const float* W2    = (const float*)d_in[11];
    const float* b2    = (const float*)d_in[12];
    float* out = (float*)d_out;

    float *h, *qkv, *o, *src2, *f, *ffn, *wq, *wo, *w1, *w2;
    cudaGetSymbolAddress((void**)&h,    g_h);
    cudaGetSymbolAddress((void**)&qkv,  g_qkv);
    cudaGetSymbolAddress((void**)&o,    g_o);
    cudaGetSymbolAddress((void**)&src2, g_src2);
    cudaGetSymbolAddress((void**)&f,    g_f);
    cudaGetSymbolAddress((void**)&ffn,  g_ffn);
    cudaGetSymbolAddress((void**)&wq,   g_wq);
    cudaGetSymbolAddress((void**)&wo,   g_wo);
    cudaGetSymbolAddress((void**)&w1,   g_w1);
    cudaGetSymbolAddress((void**)&w2,   g_w2);

    static bool inited = false;
    static cudaStream_t s2;
    static cudaEvent_t e0, e1, e2;
    if (!inited) {
        cudaStreamCreateWithFlags(&s2, cudaStreamNonBlocking);
        cudaEventCreateWithFlags(&e0, cudaEventDisableTiming);
        cudaEventCreateWithFlags(&e1, cudaEventDisableTiming);
        cudaEventCreateWithFlags(&e2, cudaEventDisableTiming);
        cudaFuncSetAttribute(mma_gemm, cudaFuncAttributeMaxDynamicSharedMemorySize, GEMM_SMEM);
        cudaFuncSetAttribute(attn_mma, cudaFuncAttributeMaxDynamicSharedMemorySize, ATTN_SMEM);
        inited = true;
    }

    // fork: wq rounding first (it gates the QKV GEMM)
    cudaEventRecord(e0, 0);
    cudaStreamWaitEvent(s2, e0, 0);
    round_w_kernel<<<(3 * DM * DM / 4 + 255) / 256, 256, 0, s2>>>((const float4*)Wqkv, wq, 3 * DM * DM / 4);
    cudaEventRecord(e1, s2);

    // 1) LN1 -> h (perm); overlaps wq rounding
    ln_kernel<<<MR, 256>>>(src, ln1_g, ln1_b, h);
    // 2) QKV: perm output features (flags 2|4)
    cudaStreamWaitEvent(0, e1, 0);
    mma_gemm<<<dim3(3 * DM / 128, MR / 128), 256, GEMM_SMEM>>>(
        h, wq, bqkv, nullptr, qkv, 3 * DM, DM, 6);
    // 3) attention -> o (perm via V); 256 uniform CTAs, single wave
    attn_mma<<<NTASK / 2, 256, ATTN_SMEM>>>(qkv, o);

    // remaining weight rounding on s2 (overlaps QKV GEMM + attention)
    round_w_kernel<<<(DM * DM / 4 + 255) / 256, 256, 0, s2>>>((const float4*)Wout, wo, DM * DM / 4);
    round_w_kernel<<<(DFF * DM / 4 + 255) / 256, 256, 0, s2>>>((const float4*)W1, w1, DFF * DM / 4);
    round_w_kernel<<<(DM * DFF / 4 + 255) / 256, 256, 0, s2>>>((const float4*)W2, w2, DM * DFF / 4);
    cudaEventRecord(e2, s2);

    // 4) out-proj: plain output
    cudaStreamWaitEvent(0, e2, 0);
    mma_gemm<<<dim3(DM / 128, MR / 128), 256, GEMM_SMEM>>>(
        o, wo, bout, src, src2, DM, DM, 0);
    // 5) LN2 -> f (perm)
    ln_kernel<<<MR, 256>>>(src2, ln2_g, ln2_b, f);
    // 6) FFN1: relu + round + perm (flags 1|2|4)
    mma_gemm<<<dim3(DFF / 128, MR / 128), 256, GEMM_SMEM>>>(
        f, w1, b1, nullptr, ffn, DFF, DM, 7);
    // 7) FFN2: plain output
    mma_gemm<<<dim3(DM / 128, MR / 128), 256, GEMM_SMEM>>>(
        ffn, w2, b2, src2, out, DM, DFF, 0);
}

// round 17
// speedup vs baseline: 1.6130x; 1.0196x over previous
#include <cuda_runtime.h>
#include <math.h>
#include <stdint.h>

// Problem constants
#define BB   2
#define SEQ  2048
#define DM   1024
#define NH   16
#define DH   64
#define DFF  4096
#define MR   (BB * SEQ)   // 4096 rows

// k-permutation within 8-groups: storage order [0,4,1,5,2,6,3,7]

// ---------------------------------------------------------------------------
// Scratch
// ---------------------------------------------------------------------------
__device__ float g_h   [(size_t)MR * DM];      // LN1 out (perm)
__device__ float g_qkv [(size_t)MR * 3 * DM];  // QKV (features perm)
__device__ float g_o   [(size_t)MR * DM];      // attn out (features perm)
__device__ float g_src2[(size_t)MR * DM];      // residual (plain)
__device__ float g_f   [(size_t)MR * DM];      // LN2 out (perm)
__device__ float g_ffn [(size_t)MR * DFF];     // FFN hidden (perm)
__device__ float g_wq  [(size_t)3 * DM * DM];  // weights: k-perm
__device__ float g_wo  [(size_t)DM * DM];
__device__ float g_w1  [(size_t)DFF * DM];
__device__ float g_w2  [(size_t)DM * DFF];

// ---------------------------------------------------------------------------
// Helpers
// ---------------------------------------------------------------------------
__device__ __forceinline__ uint32_t smem_u32(const void* p) {
    uint32_t a;
    asm("{ .reg .u64 t; cvta.to.shared.u64 t, %1; cvt.u32.u64 %0, t; }" : "=r"(a) : "l"(p));
    return a;
}
__device__ __forceinline__ float rtf32(float x) {
    uint32_t r;
    asm("cvt.rna.tf32.f32 %0, %1;" : "=r"(r) : "f"(x));
    return __uint_as_float(r);
}

#define CP16(dst, src) \
    asm volatile("cp.async.cg.shared.global [%0], [%1], 16;" :: "r"(dst), "l"(src) : "memory")
#define CP_COMMIT()  asm volatile("cp.async.commit_group;" ::: "memory")
#define CP_WAIT(n)   asm volatile("cp.async.wait_group %0;" :: "n"(n) : "memory")

__device__ __forceinline__ void mma_tf32(float* d, const uint32_t* a, const uint32_t* b) {
    asm volatile(
        "mma.sync.aligned.m16n8k8.row.col.f32.tf32.tf32.f32 "
        "{%0,%1,%2,%3}, {%4,%5,%6,%7}, {%8,%9}, {%0,%1,%2,%3};"
        : "+f"(d[0]), "+f"(d[1]), "+f"(d[2]), "+f"(d[3])
        : "r"(a[0]), "r"(a[1]), "r"(a[2]), "r"(a[3]), "r"(b[0]), "r"(b[1]));
}
__device__ __forceinline__ void mma_tf32_f(float* d, float a0, float a1, float a2, float a3,
                                           float b0, float b1) {
    asm volatile(
        "mma.sync.aligned.m16n8k8.row.col.f32.tf32.tf32.f32 "
        "{%0,%1,%2,%3}, {%4,%5,%6,%7}, {%8,%9}, {%0,%1,%2,%3};"
        : "+f"(d[0]), "+f"(d[1]), "+f"(d[2]), "+f"(d[3])
        : "r"(__float_as_uint(a0)), "r"(__float_as_uint(a1)),
          "r"(__float_as_uint(a2)), "r"(__float_as_uint(a3)),
          "r"(__float_as_uint(b0)), "r"(__float_as_uint(b1)));
}

// ---------------------------------------------------------------------------
// Tensor-core GEMM (R11 frozen): k-permuted operands + XOR swizzle
// (group' = group ^ (row & 3)) -> conflict-free LDS.64 at SMS=32.
// 3 stages, 2 CTAs/SM. CTA 128x128; 8 warps 64x32; BK=32.
// flags: 1 = relu, 2 = tf32-round, 4 = permute output features
// ---------------------------------------------------------------------------
#define ATILE  (128 * 32)
#define STF    (2 * ATILE)
#define STAGES 3
#define GEMM_SMEM (STAGES * STF * 4)   // 98304 bytes

__global__ __launch_bounds__(256, 2) void mma_gemm(
    const float* __restrict__ A, const float* __restrict__ W,
    const float* __restrict__ bias, const float* __restrict__ res,
    float* __restrict__ C, int N, int K, int flags)
{
    extern __shared__ float sm[];

    int t    = threadIdx.x;
    int wid  = t >> 5, lane = t & 31;
    int m0   = blockIdx.y * 128, n0 = blockIdx.x * 128;
    int wm   = (wid >> 2) * 64;
    int wn   = (wid & 3) * 32;
    int lr   = lane >> 2;
    int lc   = lane & 3;
    int jx   = lr & 3;

    int tr  = t >> 3;
    int lg  = (t & 7) >> 1;
    int lw  = (t & 1) * 4;
    const float* Ag = A + (size_t)(m0 + tr) * K + (t & 7) * 4;
    const float* Wg = W + (size_t)(n0 + tr) * K + (t & 7) * 4;
    uint32_t sbase = smem_u32(sm);
    uint32_t sAoff = (uint32_t)((tr * 32 + ((lg ^ (tr & 3)) << 3) + lw) * 4);
    const uint32_t rowStep = 32 * 32 * 4;

    float acc[4][4][4];
    #pragma unroll
    for (int i = 0; i < 4; i++)
        #pragma unroll
        for (int j = 0; j < 4; j++)
            #pragma unroll
            for (int k = 0; k < 4; k++) acc[i][j][k] = 0.f;

    int NK = K >> 5;

    #pragma unroll
    for (int s = 0; s < STAGES - 1; s++) {
        uint32_t sA = sbase + (uint32_t)(s * STF * 4) + sAoff;
        uint32_t sB = sA + (uint32_t)(ATILE * 4);
        const float* Ap = Ag + (size_t)s * 32;
        const float* Wp = Wg + (size_t)s * 32;
        #pragma unroll
        for (int i = 0; i < 4; i++) {
            CP16(sA + i * rowStep, Ap + (size_t)(32 * i) * K);
            CP16(sB + i * rowStep, Wp + (size_t)(32 * i) * K);
        }
        CP_COMMIT();
    }

    for (int kt = 0; kt < NK; kt++) {
        int s = kt % STAGES;
        if (kt + 1 < NK) { CP_WAIT(1); } else { CP_WAIT(0); }
        __syncthreads();

        if (kt + STAGES - 1 < NK) {
            int ls = (kt + STAGES - 1) % STAGES;
            uint32_t sA = sbase + (uint32_t)(ls * STF * 4) + sAoff;
            uint32_t sB = sA + (uint32_t)(ATILE * 4);
            const float* Ap = Ag + (size_t)(kt + STAGES - 1) * 32;
            const float* Wp = Wg + (size_t)(kt + STAGES - 1) * 32;
            #pragma unroll
            for (int i = 0; i < 4; i++) {
                CP16(sA + i * rowStep, Ap + (size_t)(32 * i) * K);
                CP16(sB + i * rowStep, Wp + (size_t)(32 * i) * K);
            }
            CP_COMMIT();
        }

        const float* Ab = sm + s * STF;
        const float* Bb = Ab + ATILE;
        #pragma unroll
        for (int ks = 0; ks < 4; ks++) {
            int kcol = ((ks ^ jx) << 3) + 2 * lc;
            uint32_t a[4][4], b[4][2];
            #pragma unroll
            for (int mt = 0; mt < 4; mt++) {
                const float2* p0 = (const float2*)(Ab + (wm + mt * 16 + lr) * 32 + kcol);
                const float2* p1 = (const float2*)(Ab + (wm + mt * 16 + lr + 8) * 32 + kcol);
                float2 v0 = *p0, v1 = *p1;
                a[mt][0] = __float_as_uint(v0.x);
                a[mt][2] = __float_as_uint(v0.y);
                a[mt][1] = __float_as_uint(v1.x);
                a[mt][3] = __float_as_uint(v1.y);
            }
            #pragma unroll
            for (int nt = 0; nt < 4; nt++) {
                const float2* p = (const float2*)(Bb + (wn + nt * 8 + lr) * 32 + kcol);
                float2 v = *p;
                b[nt][0] = __float_as_uint(v.x);
                b[nt][1] = __float_as_uint(v.y);
            }
            #pragma unroll
            for (int mt = 0; mt < 4; mt++)
                #pragma unroll
                for (int nt = 0; nt < 4; nt++)
                    mma_tf32(acc[mt][nt], a[mt], b[nt]);
        }
    }

    bool do_relu  = (flags & 1) != 0;
    bool do_round = (flags & 2) != 0;
    bool do_perm  = (flags & 4) != 0;
    int f0 = 2 * lc;
    int pos0 = (f0 < 4) ? 2 * f0 : 2 * f0 - 7;
    #pragma unroll
    for (int mt = 0; mt < 4; mt++) {
        int row = m0 + wm + mt * 16 + lr;
        #pragma unroll
        for (int nt = 0; nt < 4; nt++) {
            int colt = n0 + wn + nt * 8 + f0;
            float b0 = __ldg(&bias[colt]), b1 = __ldg(&bias[colt + 1]);
            #pragma unroll
            for (int half = 0; half < 2; half++) {
                int r = row + half * 8;
                float v0 = acc[mt][nt][half * 2 + 0] + b0;
                float v1 = acc[mt][nt][half * 2 + 1] + b1;
                if (res) {
                    const float* rp = res + (size_t)r * N + colt;
                    v0 += rp[0]; v1 += rp[1];
                }
                if (do_relu)  { v0 = fmaxf(v0, 0.f); v1 = fmaxf(v1, 0.f); }
                if (do_round) { v0 = rtf32(v0); v1 = rtf32(v1); }
                if (do_perm) {
                    float* cp = C + (size_t)r * N + n0 + wn + nt * 8;
                    cp[pos0]     = v0;
                    cp[pos0 + 2] = v1;
                } else {
                    *(float2*)(C + (size_t)r * N + colt) = make_float2(v0, v1);
                }
            }
        }
    }
}

// ---------------------------------------------------------------------------
// Round weights to tf32 AND k-permute within 8-groups
// ---------------------------------------------------------------------------
__global__ __launch_bounds__(256) void round_w_kernel(
    const float4* __restrict__ in, float* __restrict__ out, int n4)
{
    int i = blockIdx.x * blockDim.x + threadIdx.x;
    if (i < n4) {
        float4 v = in[i];
        size_t f0 = (size_t)i * 4;
        size_t ob = (f0 & ~(size_t)7) + ((f0 >> 2) & 1);
        out[ob + 0] = rtf32(v.x);
        out[ob + 2] = rtf32(v.y);
        out[ob + 4] = rtf32(v.z);
        out[ob + 6] = rtf32(v.w);
    }
}

// ---------------------------------------------------------------------------
// LayerNorm: tf32-rounded, k-permuted output
// ---------------------------------------------------------------------------
__global__ __launch_bounds__(256) void ln_kernel(
    const float* __restrict__ x, const float* __restrict__ g,
    const float* __restrict__ bt, float* __restrict__ y)
{
    int row = blockIdx.x;
    int t = threadIdx.x;
    const float* xr = x + (size_t)row * DM;

    float4 v = *(const float4*)(xr + t * 4);
    float s  = v.x + v.y + v.z + v.w;
    float ss = v.x * v.x + v.y * v.y + v.z * v.z + v.w * v.w;

    #pragma unroll
    for (int o = 16; o; o >>= 1) {
        s  += __shfl_xor_sync(0xffffffffu, s,  o);
        ss += __shfl_xor_sync(0xffffffffu, ss, o);
    }
    __shared__ float rs[8], rss[8];
    if ((t & 31) == 0) { rs[t >> 5] = s; rss[t >> 5] = ss; }
    __syncthreads();
    if (t < 32) {
        float a  = (t < 8) ? rs[t]  : 0.f;
        float bb = (t < 8) ? rss[t] : 0.f;
        #pragma unroll
        for (int o = 4; o; o >>= 1) {
            a  += __shfl_xor_sync(0xffffffffu, a,  o);
            bb += __shfl_xor_sync(0xffffffffu, bb, o);
        }
        if (t == 0) { rs[0] = a; rss[0] = bb; }
    }
    __syncthreads();
    float mean = rs[0] * (1.f / DM);
    float var  = rss[0] * (1.f / DM) - mean * mean;
    float rstd = rsqrtf(var + 1e-5f);

    float4 gv = *(const float4*)(g  + t * 4);
    float4 bv = *(const float4*)(bt + t * 4);
    float o0 = rtf32((v.x - mean) * rstd * gv.x + bv.x);
    float o1 = rtf32((v.y - mean) * rstd * gv.y + bv.y);
    float o2 = rtf32((v.z - mean) * rstd * gv.z + bv.z);
    float o3 = rtf32((v.w - mean) * rstd * gv.w + bv.w);
    int f0 = t * 4;
    float* yp = y + (size_t)row * DM + (f0 & ~7) + ((f0 >> 2) & 1);
    yp[0] = o0; yp[2] = o1; yp[4] = o2; yp[6] = o3;
}

// ---------------------------------------------------------------------------
// Attention (R16 + balanced 296-CTA schedule + fused exp/PV):
//  - bins 0..79 solo (heaviest tasks); bins 80..295 pair with task 591-bid
//    -> per-slot max 32 kt-units, grid 296 = exactly 2 CTAs on every SM.
//  - exp2/causal/l-sum fused into the PV key-group loop (MUFU/tensor overlap,
//    identical per-thread arithmetic order).
// ---------------------------------------------------------------------------
#define ATS  72                         // K tile / Q stage stride
#define ATSV 68                         // V tile stride
#define KVBK (64 * ATS)
#define KVBV (64 * ATSV)
#define ATTN_SMEM ((2 * KVBK + 2 * KVBV + 128 * ATS) * 4)   // 108544 bytes
#define LOG2E 1.4426950408889634f
#define NTASK (32 * (SEQ / 128))        // 512
#define ATTN_GRID 296

__global__ __launch_bounds__(256, 2) void attn_mma(
    const float* __restrict__ qkv, float* __restrict__ o)
{
    extern __shared__ float sm[];
    float* KsB = sm;                    // [2][64][72]
    float* VsB = sm + 2 * KVBK;         // [2][64][68]
    float* Ps  = sm + 2 * KVBK + 2 * KVBV;   // [128][72] (Q stage only)

    int t = threadIdx.x, wid = t >> 5, lane = t & 31;
    int lr = lane >> 2, lc = lane & 3;
    int wr = wid * 16;
    int bid = (int)blockIdx.x;

    int lv_r = t >> 2, lv_c = (t & 3) * 16;
    uint32_t ks_base = smem_u32(KsB) + (uint32_t)((lv_r * ATS  + lv_c) * 4);
    uint32_t vs_base = smem_u32(VsB) + (uint32_t)((lv_r * ATSV + lv_c) * 4);

    #pragma unroll 1
    for (int ti = 0; ti < 2; ti++) {
        int tau;
        if (ti == 0) {
            tau = bid;                       // tasks 0..295 (heaviest first)
        } else {
            if (bid < 80) break;             // bins 0..79 run solo
            tau = 591 - bid;                 // tasks 296..511 (lightest)
        }
        int qt  = (SEQ / 128 - 1) - (tau >> 5);
        int bh  = tau & 31;
        int b = bh >> 4, h = bh & 15;
        int q0 = qt * 128;
        float slope = exp2f(-(float)h) * LOG2E;

        const float* base = qkv + (size_t)(b * SEQ) * (3 * DM) + h * DH;

        __syncthreads();   // previous task done with Ps and KV buffers

        // stage Q (x 0.125*log2(e)); verbatim copy preserves permuted layout
        {
            int r = t >> 1, cb = (t & 1) * 32;
            const float* qp = base + (size_t)(q0 + r) * (3 * DM) + cb;
            float* pp = Ps + r * ATS + cb;
            const float qs = 0.125f * LOG2E;
            #pragma unroll
            for (int i = 0; i < 8; i++) {
                float4 v = *(const float4*)(qp + i * 4);
                v.x *= qs; v.y *= qs; v.z *= qs; v.w *= qs;
                *(float4*)(pp + i * 4) = v;
            }
        }
        __syncthreads();
        uint32_t qf[8][4];
        #pragma unroll
        for (int ks = 0; ks < 8; ks++) {
            const float2* p0 = (const float2*)(Ps + (wr + lr) * ATS + ks * 8 + 2 * lc);
            const float2* p1 = (const float2*)(Ps + (wr + lr + 8) * ATS + ks * 8 + 2 * lc);
            float2 v0 = *p0, v1 = *p1;
            qf[ks][0] = __float_as_uint(v0.x);
            qf[ks][2] = __float_as_uint(v0.y);
            qf[ks][1] = __float_as_uint(v1.x);
            qf[ks][3] = __float_as_uint(v1.y);
        }

        float oacc[8][4];
        #pragma unroll
        for (int nt = 0; nt < 8; nt++)
            #pragma unroll
            for (int k = 0; k < 4; k++) oacc[nt][k] = 0.f;
        float l0 = 0.f, l1 = 0.f;
        int r0 = q0 + wr + lr, r1 = r0 + 8;

        int ktmax = 2 * qt + 1;

        // prologue: load kt=0 into buf 0
        {
            const float* kp = base + (size_t)lv_r * (3 * DM) + DM + lv_c;
            #pragma unroll
            for (int i = 0; i < 4; i++) {
                CP16(ks_base + i * 16, kp + i * 4);
                CP16(vs_base + i * 16, kp + DM + i * 4);
            }
            CP_COMMIT();
        }

        for (int kt = 0; kt <= ktmax; kt++) {
            int buf = kt & 1;
            CP_WAIT(0);
            __syncthreads();

            // prefetch kt+1 into buf^1 (overlaps compute below)
            if (kt < ktmax) {
                uint32_t offK = (uint32_t)((buf ^ 1) * KVBK * 4);
                uint32_t offV = (uint32_t)((buf ^ 1) * KVBV * 4);
                const float* kp = base + (size_t)((kt + 1) * 64 + lv_r) * (3 * DM) + DM + lv_c;
                #pragma unroll
                for (int i = 0; i < 4; i++) {
                    CP16(ks_base + offK + i * 16, kp + i * 4);
                    CP16(vs_base + offV + i * 16, kp + DM + i * 4);
                }
                CP_COMMIT();
            }

            const float* Kst = KsB + buf * KVBK;
            const float* Vst = VsB + buf * KVBV;

            int jb = kt * 64;

            // S = Q K^T, column bias -j*slope in accumulator init
            float sacc[8][4];
            #pragma unroll
            for (int nt = 0; nt < 8; nt++) {
                float bj0 = -(float)(jb + nt * 8 + 2 * lc) * slope;
                float bj1 = bj0 - slope;
                sacc[nt][0] = bj0; sacc[nt][1] = bj1;
                sacc[nt][2] = bj0; sacc[nt][3] = bj1;
            }
            #pragma unroll
            for (int ks = 0; ks < 8; ks++) {
                uint32_t bf[8][2];
                #pragma unroll
                for (int nt = 0; nt < 8; nt++) {
                    const float2* p = (const float2*)(Kst + (nt * 8 + lr) * ATS + ks * 8 + 2 * lc);
                    float2 v = *p;
                    bf[nt][0] = __float_as_uint(v.x);
                    bf[nt][1] = __float_as_uint(v.y);
                }
                #pragma unroll
                for (int nt = 0; nt < 8; nt++)
                    mma_tf32(sacc[nt], qf[ks], bf[nt]);
            }

            // fused: per key-group g -> exp2/causal/l-sum, then PV MMAs
            #pragma unroll
            for (int g = 0; g < 8; g++) {
                int j0 = jb + g * 8 + 2 * lc;
                int j1 = j0 + 1;
                float e0 = exp2f(sacc[g][0]);
                float e1 = exp2f(sacc[g][1]);
                float e2 = exp2f(sacc[g][2]);
                float e3 = exp2f(sacc[g][3]);
                if (j0 > r0) e0 = 0.f;
                if (j1 > r0) e1 = 0.f;
                if (j0 > r1) e2 = 0.f;
                if (j1 > r1) e3 = 0.f;
                l0 += e0 + e1;
                l1 += e2 + e3;
                const float* vp = Vst + (g * 8 + 2 * lc) * ATSV;
                #pragma unroll
                for (int nt = 0; nt < 8; nt++) {
                    const float* vq = vp + nt * 8 + lr;
                    mma_tf32_f(oacc[nt], e0, e2, e1, e3, vq[0], vq[ATSV]);
                }
            }
        }

        l0 += __shfl_xor_sync(0xffffffffu, l0, 1);
        l0 += __shfl_xor_sync(0xffffffffu, l0, 2);
        l1 += __shfl_xor_sync(0xffffffffu, l1, 1);
        l1 += __shfl_xor_sync(0xffffffffu, l1, 2);

        float inv0 = 1.f / l0, inv1 = 1.f / l1;
        float* op0 = o + (size_t)(b * SEQ + q0 + wr + lr) * DM + h * DH;
        float* op1 = op0 + (size_t)8 * DM;
        #pragma unroll
        for (int nt = 0; nt < 8; nt++) {
            *(float2*)(op0 + nt * 8 + 2 * lc) =
                make_float2(rtf32(oacc[nt][0] * inv0), rtf32(oacc[nt][1] * inv0));
            *(float2*)(op1 + nt * 8 + 2 * lc) =
                make_float2(rtf32(oacc[nt][2] * inv1), rtf32(oacc[nt][3] * inv1));
        }
    }
}

// ---------------------------------------------------------------------------
// Launch
// ---------------------------------------------------------------------------
extern "C" void kernel_launch(void* const* d_in, const int* in_sizes, int n_in,
                              void* d_out, int out_size)
{
    const float* src   = (const float*)d_in[0];
    const float* ln1_g = (const float*)d_in[1];
    const float* ln1_b = (const float*)d_in[2];
    const float* Wqkv  = (const float*)d_in[3];
    const float* bqkv  = (const float*)d_in[4];
    const float* Wout  = (const float*)d_in[5];
    const float* bout  = (const float*)d_in[6];
    const float* ln2_g = (const float*)d_in[7];
    const float* ln2_b = (const float*)d_in[8];
    const float* W1    = (const float*)d_in[9];
    const float* b1    = (const float*)d_in[10];
    const float* W2    = (const float*)d_in[11];
    const float* b2    = (const float*)d_in[12];
    float* out = (float*)d_out;

    float *h, *qkv, *o, *src2, *f, *ffn, *wq, *wo, *w1, *w2;
    cudaGetSymbolAddress((void**)&h,    g_h);
    cudaGetSymbolAddress((void**)&qkv,  g_qkv);
    cudaGetSymbolAddress((void**)&o,    g_o);
    cudaGetSymbolAddress((void**)&src2, g_src2);
    cudaGetSymbolAddress((void**)&f,    g_f);
    cudaGetSymbolAddress((void**)&ffn,  g_ffn);
    cudaGetSymbolAddress((void**)&wq,   g_wq);
    cudaGetSymbolAddress((void**)&wo,   g_wo);
    cudaGetSymbolAddress((void**)&w1,   g_w1);
    cudaGetSymbolAddress((void**)&w2,   g_w2);

    static bool inited = false;
    static cudaStream_t s2;
    static cudaEvent_t e0, e1, e2;
    if (!inited) {
        cudaStreamCreateWithFlags(&s2, cudaStreamNonBlocking);
        cudaEventCreateWithFlags(&e0, cudaEventDisableTiming);
        cudaEventCreateWithFlags(&e1, cudaEventDisableTiming);
        cudaEventCreateWithFlags(&e2, cudaEventDisableTiming);
        cudaFuncSetAttribute(mma_gemm, cudaFuncAttributeMaxDynamicSharedMemorySize, GEMM_SMEM);
        cudaFuncSetAttribute(attn_mma, cudaFuncAttributeMaxDynamicSharedMemorySize, ATTN_SMEM);
        inited = true;
    }

    // fork: wq rounding first (it gates the QKV GEMM)
    cudaEventRecord(e0, 0);
    cudaStreamWaitEvent(s2, e0, 0);
    round_w_kernel<<<(3 * DM * DM / 4 + 255) / 256, 256, 0, s2>>>((const float4*)Wqkv, wq, 3 * DM * DM / 4);
    cudaEventRecord(e1, s2);

    // 1) LN1 -> h (perm); overlaps wq rounding
    ln_kernel<<<MR, 256>>>(src, ln1_g, ln1_b, h);
    // 2) QKV: perm output features (flags 2|4)
    cudaStreamWaitEvent(0, e1, 0);
    mma_gemm<<<dim3(3 * DM / 128, MR / 128), 256, GEMM_SMEM>>>(
        h, wq, bqkv, nullptr, qkv, 3 * DM, DM, 6);
    // 3) attention -> o (perm via V); 296 balanced CTAs, exactly 1 wave
    attn_mma<<<ATTN_GRID, 256, ATTN_SMEM>>>(qkv, o);

    // remaining weight rounding on s2 (overlaps QKV GEMM + attention)
    round_w_kernel<<<(DM * DM / 4 + 255) / 256, 256, 0, s2>>>((const float4*)Wout, wo, DM * DM / 4);
    round_w_kernel<<<(DFF * DM / 4 + 255) / 256, 256, 0, s2>>>((const float4*)W1, w1, DFF * DM / 4);
    round_w_kernel<<<(DM * DFF / 4 + 255) / 256, 256, 0, s2>>>((const float4*)W2, w2, DM * DFF / 4);
    cudaEventRecord(e2, s2);

    // 4) out-proj: plain output
    cudaStreamWaitEvent(0, e2, 0);
    mma_gemm<<<dim3(DM / 128, MR / 128), 256, GEMM_SMEM>>>(
        o, wo, bout, src, src2, DM, DM, 0);
    // 5) LN2 -> f (perm)
    ln_kernel<<<MR, 256>>>(src2, ln2_g, ln2_b, f);
    // 6) FFN1: relu + round + perm (flags 1|2|4)
    mma_gemm<<<dim3(DFF / 128, MR / 128), 256, GEMM_SMEM>>>(
        f, w1, b1, nullptr, ffn, DFF, DM, 7);
    // 7) FFN2: plain output
    mma_gemm<<<dim3(DM / 128, MR / 128), 256, GEMM_SMEM>>>(
        ffn, w2, b2, src2, out, DM, DFF, 0);
}